// round 11
// baseline (speedup 1.0000x reference)
#include <cuda_runtime.h>
#include <cuda_fp16.h>
#include <cstdint>
#include <math.h>

#define S_DIM 2048
#define A_DIM 64
#define P_DIM 128
#define B_SZ 256
#define T_STEPS 32
#define HS_DIM (S_DIM + A_DIM + P_DIM)   // 2240
#define ALP 256                          // padded K for act/latent GEMM
#define PRED_ELEMS ((size_t)T_STEPS * B_SZ * S_DIM)

// ---------------- device scratch (static, no allocations) ----------------
__device__ __half g_Wh   [S_DIM * S_DIM];
__device__ __half g_Wap  [S_DIM * ALP];
__device__ __half g_fc1e [S_DIM * S_DIM];
__device__ __half g_fc2  [S_DIM * S_DIM];
__device__ __half g_WWi  [4 * S_DIM * S_DIM];
__device__ __half g_al   [T_STEPS * B_SZ * ALP];
__device__ __half g_s0   [B_SZ * S_DIM];
__device__ float  g_abias[T_STEPS * B_SZ * S_DIM];
__device__ __half g_hn   [B_SZ * S_DIM];
__device__ __half g_h    [B_SZ * S_DIM];
__device__ __half g_x1   [B_SZ * S_DIM];
__device__ __half g_x2   [B_SZ * S_DIM];
__device__ float  g_c    [B_SZ * S_DIM];
__device__ float  g_part [2 * B_SZ * S_DIM];    // split-K partials (4MB)
__device__ int    g_tcnt [64];                  // per-tile arrival counters (mod-SPLIT)

// ---------------- helpers ----------------
__device__ __forceinline__ void cp16(void* sdst, const void* gsrc) {
    unsigned s = (unsigned)__cvta_generic_to_shared(sdst);
    asm volatile("cp.async.cg.shared.global [%0], [%1], 16;\n" :: "r"(s), "l"(gsrc));
}

__device__ __forceinline__ void ldsm_x4(uint32_t& r0, uint32_t& r1, uint32_t& r2, uint32_t& r3,
                                        const __half* p) {
    uint32_t a = (uint32_t)__cvta_generic_to_shared(p);
    asm volatile("ldmatrix.sync.aligned.m8n8.x4.shared.b16 {%0,%1,%2,%3}, [%4];\n"
                 : "=r"(r0), "=r"(r1), "=r"(r2), "=r"(r3) : "r"(a));
}

__device__ __forceinline__ void mma_f16(float c[4],
                                        uint32_t a0, uint32_t a1, uint32_t a2, uint32_t a3,
                                        uint32_t b0, uint32_t b1) {
    asm volatile(
        "mma.sync.aligned.m16n8k16.row.col.f32.f16.f16.f32 "
        "{%0,%1,%2,%3}, {%4,%5,%6,%7}, {%8,%9}, {%0,%1,%2,%3};\n"
        : "+f"(c[0]), "+f"(c[1]), "+f"(c[2]), "+f"(c[3])
        : "r"(a0), "r"(a1), "r"(a2), "r"(a3), "r"(b0), "r"(b1));
}

#define LDSH 136   // halves per smem row (128 data + 8 pad); 272 B

// ================= 128x128 HMMA GEMM (warp tile 64x32), optional split-K =================
// A:[M,K], B:[N,K] fp16 row-major. blockIdx.z = K-slice. BK=128, 3 stages.
// SPLIT==1: direct epilogue. SPLIT>1: fp32 partial + counter; last CTA reduces
// in fixed z-order (deterministic) and applies bias/relu/conversion.
template<int SPLIT, bool RELU>
__global__ void __launch_bounds__(256, 1) gemm_splitk(
    const __half* __restrict__ A, const __half* __restrict__ Bm,
    float* __restrict__ part,
    float* __restrict__ outF, __half* __restrict__ outH,
    const float* __restrict__ colBias, const float* __restrict__ elemBias,
    int N, int K)
{
    constexpr int BM = 128, BN = 128, WR = 2, WC = 4;
    constexpr int NTH = 256;
    constexpr int NSTG = 3;
    constexpr int WM = BM / WR, WN = BN / WC;   // 64, 32
    constexpr int MF = WM / 16, NF = WN / 8;    // 4, 4
    constexpr int ROWS = BM + BN;               // 256
    constexpr int ITER = ROWS * 16 / NTH;       // 16

    extern __shared__ __half sm[];
    __shared__ int s_last;

    const int tid  = threadIdx.x;
    const int warp = tid >> 5;
    const int lane = tid & 31;
    const int wm = warp / WC;
    const int wn = warp % WC;
    const int g  = lane >> 2;
    const int tg = lane & 3;
    const int lr = lane & 7;
    const int lq = lane >> 3;

    const int z     = blockIdx.z;
    const int Ksl   = K / SPLIT;
    const int mbase = blockIdx.y * BM;
    const int nbase = blockIdx.x * BN;
    const __half* Ab = A  + (size_t)mbase * K + (size_t)z * Ksl;
    const __half* Bb = Bm + (size_t)nbase * K + (size_t)z * Ksl;
    const int nk = Ksl >> 7;

    float acc[MF][NF][4];
#pragma unroll
    for (int i = 0; i < MF; i++)
#pragma unroll
        for (int j = 0; j < NF; j++)
#pragma unroll
            for (int e = 0; e < 4; e++) acc[i][j][e] = 0.f;

    auto load_stage = [&](int st, int kb) {
        const int k0 = kb * 128;
        __half* Ao = sm + (size_t)st * ROWS * LDSH;
        __half* Bo = Ao + (size_t)BM * LDSH;
#pragma unroll
        for (int i = 0; i < ITER; i++) {
            int id  = tid + i * NTH;
            int row = id >> 4;
            int kc  = (id & 15) * 8;
            if (row < BM)
                cp16(Ao + (size_t)row * LDSH + kc, Ab + (size_t)row * K + k0 + kc);
            else
                cp16(Bo + (size_t)(row - BM) * LDSH + kc,
                     Bb + (size_t)(row - BM) * K + k0 + kc);
        }
        asm volatile("cp.async.commit_group;\n" ::: "memory");
    };

    if (0 < nk) load_stage(0, 0);
    if (1 < nk) load_stage(1, 1);

    uint32_t a[2][MF][4];
    uint32_t b[2][NF][2];

    for (int kb = 0; kb < nk; kb++) {
        const int rem = nk - 1 - kb;
        const int allow = rem < NSTG - 2 ? rem : NSTG - 2;
        if (allow >= 1) asm volatile("cp.async.wait_group 1;\n" ::: "memory");
        else            asm volatile("cp.async.wait_group 0;\n" ::: "memory");
        __syncthreads();

        if (kb + 2 < nk) load_stage((kb + 2) % NSTG, kb + 2);

        const int st = kb % NSTG;
        const __half* Abase = sm + (size_t)st * ROWS * LDSH;
        const __half* Bbase = Abase + (size_t)BM * LDSH;

        auto load_frag = [&](int buf, int k0) {
#pragma unroll
            for (int mf = 0; mf < MF; mf++) {
                int row = wm * WM + mf * 16 + (lq & 1) * 8 + lr;
                int col = k0 + (lq >> 1) * 8;
                ldsm_x4(a[buf][mf][0], a[buf][mf][1], a[buf][mf][2], a[buf][mf][3],
                        Abase + (size_t)row * LDSH + col);
            }
#pragma unroll
            for (int np = 0; np < NF / 2; np++) {
                int row = wn * WN + np * 16 + (lq >> 1) * 8 + lr;
                int col = k0 + (lq & 1) * 8;
                uint32_t r0, r1, r2, r3;
                ldsm_x4(r0, r1, r2, r3, Bbase + (size_t)row * LDSH + col);
                b[buf][2 * np][0] = r0; b[buf][2 * np][1] = r1;
                b[buf][2 * np + 1][0] = r2; b[buf][2 * np + 1][1] = r3;
            }
        };

        load_frag(0, 0);
#pragma unroll
        for (int ks = 0; ks < 8; ks++) {
            const int cur = ks & 1;
            if (ks < 7) load_frag(cur ^ 1, (ks + 1) * 16);
#pragma unroll
            for (int mf = 0; mf < MF; mf++)
#pragma unroll
                for (int nf = 0; nf < NF; nf++)
                    mma_f16(acc[mf][nf], a[cur][mf][0], a[cur][mf][1],
                            a[cur][mf][2], a[cur][mf][3],
                            b[cur][nf][0], b[cur][nf][1]);
        }
    }

    if (SPLIT == 1) {
#pragma unroll
        for (int nf = 0; nf < NF; nf++) {
            int col = nbase + wn * WN + nf * 8 + 2 * tg;
            float cb0 = colBias ? colBias[col]     : 0.f;
            float cb1 = colBias ? colBias[col + 1] : 0.f;
#pragma unroll
            for (int mf = 0; mf < MF; mf++) {
                int row = mbase + wm * WM + mf * 16 + g;
                size_t o0 = (size_t)row * N + col;
                size_t o1 = (size_t)(row + 8) * N + col;
                float v00 = acc[mf][nf][0] + cb0;
                float v01 = acc[mf][nf][1] + cb1;
                float v10 = acc[mf][nf][2] + cb0;
                float v11 = acc[mf][nf][3] + cb1;
                if (RELU) {
                    v00 = fmaxf(v00, 0.f); v01 = fmaxf(v01, 0.f);
                    v10 = fmaxf(v10, 0.f); v11 = fmaxf(v11, 0.f);
                }
                if (outF) {
                    *(float2*)(outF + o0) = make_float2(v00, v01);
                    *(float2*)(outF + o1) = make_float2(v10, v11);
                }
                if (outH) {
                    *(__half2*)(outH + o0) = __floats2half2_rn(v00, v01);
                    *(__half2*)(outH + o1) = __floats2half2_rn(v10, v11);
                }
            }
        }
        return;
    }

    // split-K: store fp32 partial slice
    const size_t MN = (size_t)B_SZ * N;
    float* myp = part + (size_t)z * MN;
#pragma unroll
    for (int nf = 0; nf < NF; nf++) {
        int col = nbase + wn * WN + nf * 8 + 2 * tg;
#pragma unroll
        for (int mf = 0; mf < MF; mf++) {
            int row = mbase + wm * WM + mf * 16 + g;
            size_t o0 = (size_t)row * N + col;
            size_t o1 = (size_t)(row + 8) * N + col;
            *(float2*)(myp + o0) = make_float2(acc[mf][nf][0], acc[mf][nf][1]);
            *(float2*)(myp + o1) = make_float2(acc[mf][nf][2], acc[mf][nf][3]);
        }
    }
    __threadfence();
    __syncthreads();
    if (tid == 0) {
        int tile = blockIdx.y * gridDim.x + blockIdx.x;
        int v = atomicAdd(&g_tcnt[tile], 1) + 1;
        s_last = ((v % SPLIT) == 0) ? 1 : 0;
    }
    __syncthreads();
    if (!s_last) return;
    __threadfence();

    // last CTA: reduce in fixed z-order + epilogue
#pragma unroll
    for (int nf = 0; nf < NF; nf++) {
        int col = nbase + wn * WN + nf * 8 + 2 * tg;
        float cb0 = colBias ? colBias[col]     : 0.f;
        float cb1 = colBias ? colBias[col + 1] : 0.f;
#pragma unroll
        for (int mf = 0; mf < MF; mf++) {
            int row = mbase + wm * WM + mf * 16 + g;
            size_t o0 = (size_t)row * N + col;
            size_t o1 = (size_t)(row + 8) * N + col;
            float v00 = 0.f, v01 = 0.f, v10 = 0.f, v11 = 0.f;
#pragma unroll
            for (int zz = 0; zz < SPLIT; zz++) {
                if (zz == z) {
                    v00 += acc[mf][nf][0]; v01 += acc[mf][nf][1];
                    v10 += acc[mf][nf][2]; v11 += acc[mf][nf][3];
                } else {
                    float2 p0 = __ldcg((const float2*)(part + (size_t)zz * MN + o0));
                    float2 p1 = __ldcg((const float2*)(part + (size_t)zz * MN + o1));
                    v00 += p0.x; v01 += p0.y; v10 += p1.x; v11 += p1.y;
                }
            }
            if (elemBias) {
                float2 ea = *(const float2*)(elemBias + o0);
                float2 eb = *(const float2*)(elemBias + o1);
                v00 += ea.x; v01 += ea.y; v10 += eb.x; v11 += eb.y;
            }
            v00 += cb0; v01 += cb1; v10 += cb0; v11 += cb1;
            if (RELU) {
                v00 = fmaxf(v00, 0.f); v01 = fmaxf(v01, 0.f);
                v10 = fmaxf(v10, 0.f); v11 = fmaxf(v11, 0.f);
            }
            if (outF) {
                *(float2*)(outF + o0) = make_float2(v00, v01);
                *(float2*)(outF + o1) = make_float2(v10, v11);
            }
            if (outH) {
                *(__half2*)(outH + o0) = __floats2half2_rn(v00, v01);
                *(__half2*)(outH + o1) = __floats2half2_rn(v10, v11);
            }
        }
    }
}

// ================= WW GEMM + gates (256 threads, warp tile 64x32) =================
__global__ void __launch_bounds__(256, 1) ww_gates_fused(
    const __half* __restrict__ A, const __half* __restrict__ Bm,
    float* __restrict__ cell, __half* __restrict__ hn,
    float* __restrict__ preds, float* __restrict__ rewards,
    const float* __restrict__ rW, int t)
{
    constexpr int BM = 128, BN = 128, WR = 2, WC = 4;
    constexpr int NTH = 256;
    constexpr int NSTG = 3;
    constexpr int WM = BM / WR, WN = BN / WC;   // 64, 32
    constexpr int MF = WM / 16, NF = WN / 8;    // 4, 4
    constexpr int ROWS = BM + BN;
    constexpr int ITER = ROWS * 16 / NTH;       // 16
    constexpr int K = S_DIM;
    constexpr int nk = K / 128;                 // 16
    constexpr int EST = 132;

    extern __shared__ __half sm[];

    const int tid  = threadIdx.x;
    const int warp = tid >> 5;
    const int lane = tid & 31;
    const int wm = warp / WC;
    const int wn = warp % WC;
    const int g  = lane >> 2;
    const int tg = lane & 3;
    const int lr = lane & 7;
    const int lq = lane >> 3;

    const int mbase = blockIdx.y * BM;
    const int nbase = blockIdx.x * BN;
    const __half* Ab = A  + (size_t)mbase * K;
    const __half* Bb = Bm + (size_t)nbase * K;

    float acc[MF][NF][4];
#pragma unroll
    for (int i = 0; i < MF; i++)
#pragma unroll
        for (int j = 0; j < NF; j++)
#pragma unroll
            for (int e = 0; e < 4; e++) acc[i][j][e] = 0.f;

    auto load_stage = [&](int st, int kb) {
        const int k0 = kb * 128;
        __half* Ao = sm + (size_t)st * ROWS * LDSH;
        __half* Bo = Ao + (size_t)BM * LDSH;
#pragma unroll
        for (int i = 0; i < ITER; i++) {
            int id  = tid + i * NTH;
            int row = id >> 4;
            int kc  = (id & 15) * 8;
            if (row < BM)
                cp16(Ao + (size_t)row * LDSH + kc, Ab + (size_t)row * K + k0 + kc);
            else
                cp16(Bo + (size_t)(row - BM) * LDSH + kc,
                     Bb + (size_t)(row - BM) * K + k0 + kc);
        }
        asm volatile("cp.async.commit_group;\n" ::: "memory");
    };

    load_stage(0, 0);
    load_stage(1, 1);

    uint32_t a[2][MF][4];
    uint32_t b[2][NF][2];

    for (int kb = 0; kb < nk; kb++) {
        const int rem = nk - 1 - kb;
        const int allow = rem < NSTG - 2 ? rem : NSTG - 2;
        if (allow >= 1) asm volatile("cp.async.wait_group 1;\n" ::: "memory");
        else            asm volatile("cp.async.wait_group 0;\n" ::: "memory");
        __syncthreads();

        if (kb + 2 < nk) load_stage((kb + 2) % NSTG, kb + 2);

        const int st = kb % NSTG;
        const __half* Abase = sm + (size_t)st * ROWS * LDSH;
        const __half* Bbase = Abase + (size_t)BM * LDSH;

        auto load_frag = [&](int buf, int k0) {
#pragma unroll
            for (int mf = 0; mf < MF; mf++) {
                int row = wm * WM + mf * 16 + (lq & 1) * 8 + lr;
                int col = k0 + (lq >> 1) * 8;
                ldsm_x4(a[buf][mf][0], a[buf][mf][1], a[buf][mf][2], a[buf][mf][3],
                        Abase + (size_t)row * LDSH + col);
            }
#pragma unroll
            for (int np = 0; np < NF / 2; np++) {
                int row = wn * WN + np * 16 + (lq >> 1) * 8 + lr;
                int col = k0 + (lq & 1) * 8;
                uint32_t r0, r1, r2, r3;
                ldsm_x4(r0, r1, r2, r3, Bbase + (size_t)row * LDSH + col);
                b[buf][2 * np][0] = r0; b[buf][2 * np][1] = r1;
                b[buf][2 * np + 1][0] = r2; b[buf][2 * np + 1][1] = r3;
            }
        };

        load_frag(0, 0);
#pragma unroll
        for (int ks = 0; ks < 8; ks++) {
            const int cur = ks & 1;
            if (ks < 7) load_frag(cur ^ 1, (ks + 1) * 16);
#pragma unroll
            for (int mf = 0; mf < MF; mf++)
#pragma unroll
                for (int nf = 0; nf < NF; nf++)
                    mma_f16(acc[mf][nf], a[cur][mf][0], a[cur][mf][1],
                            a[cur][mf][2], a[cur][mf][3],
                            b[cur][nf][0], b[cur][nf][1]);
        }
    }

    __syncthreads();
    float* smf = (float*)sm;
#pragma unroll
    for (int nf = 0; nf < NF; nf++) {
        int col = wn * WN + nf * 8 + 2 * tg;
#pragma unroll
        for (int mf = 0; mf < MF; mf++) {
            int row = wm * WM + mf * 16 + g;
            *(float2*)&smf[(size_t)row * EST + col]       = make_float2(acc[mf][nf][0], acc[mf][nf][1]);
            *(float2*)&smf[(size_t)(row + 8) * EST + col] = make_float2(acc[mf][nf][2], acc[mf][nf][3]);
        }
    }
    __syncthreads();

    const int b_local = tid >> 1;
    const int bb = mbase + b_local;
    float rsum = 0.f;
#pragma unroll
    for (int i = 0; i < 16; i++) {
        int s_local = (tid & 1) * 16 + i;
        float4 q = *(float4*)&smf[(size_t)b_local * EST + 4 * s_local];
        float ci = fmaxf(q.x, 0.f);
        float cf = fmaxf(q.y, 0.f);
        float co = fmaxf(q.z, 0.f);
        float cg = fmaxf(q.w, 0.f);
        float ig = 1.f / (1.f + expf(-ci));
        float fg = 1.f / (1.f + expf(-cf));
        float og = 1.f / (1.f + expf(-co));
        float gg = tanhf(cg);
        int s_glob = (nbase >> 2) + s_local;
        size_t cidx = (size_t)bb * S_DIM + s_glob;
        float cn = fg * cell[cidx] + ig * gg;
        float hnv = og * tanhf(cn);
        cell[cidx] = cn;
        preds[((size_t)t * B_SZ + bb) * S_DIM + s_glob] = hnv;
        hn[(size_t)bb * S_DIM + s_glob] = __float2half(hnv);
        rsum += hnv * rW[s_glob];
    }
    rsum += __shfl_xor_sync(0xffffffffu, rsum, 1);
    if (!(tid & 1)) atomicAdd(&rewards[t * B_SZ + bb], rsum);
}

// ---------------- precompute kernels ----------------
__global__ void pack_w_kernel(const float* __restrict__ fcW) {
    const int n1 = S_DIM * S_DIM;
    for (int i = blockIdx.x * blockDim.x + threadIdx.x; i < n1; i += gridDim.x * blockDim.x) {
        int nr = i / S_DIM, k = i % S_DIM;
        g_Wh[i] = __float2half(fcW[(size_t)nr * HS_DIM + k]);
    }
    const int n2 = S_DIM * ALP;
    for (int i = blockIdx.x * blockDim.x + threadIdx.x; i < n2; i += gridDim.x * blockDim.x) {
        int nr = i / ALP, c = i % ALP;
        float v = (c < A_DIM + P_DIM) ? fcW[(size_t)nr * HS_DIM + S_DIM + c] : 0.f;
        g_Wap[i] = __float2half(v);
    }
}

__global__ void al_init_kernel(const float* __restrict__ state,
                               const float* __restrict__ act,
                               const float* __restrict__ latent,
                               float* __restrict__ rewards,
                               const float* __restrict__ rb) {
    const int n1 = T_STEPS * B_SZ * ALP;
    for (int i = blockIdx.x * blockDim.x + threadIdx.x; i < n1; i += gridDim.x * blockDim.x) {
        int r = i / ALP, c = i % ALP;
        int t = r / B_SZ, b = r % B_SZ;
        float v;
        if (c < A_DIM)              v = act[((size_t)b * T_STEPS + t) * A_DIM + c];
        else if (c < A_DIM + P_DIM) v = latent[(size_t)b * P_DIM + (c - A_DIM)];
        else                        v = 0.f;
        g_al[i] = __float2half(v);
    }
    const int n2 = B_SZ * S_DIM;
    for (int i = blockIdx.x * blockDim.x + threadIdx.x; i < n2; i += gridDim.x * blockDim.x)
        g_s0[i] = __float2half(state[i]);
    for (int i = blockIdx.x * blockDim.x + threadIdx.x; i < T_STEPS * B_SZ;
         i += gridDim.x * blockDim.x)
        rewards[i] = rb[0];
}

__global__ void fc1fold_kernel(const float* __restrict__ fc1) {
    const int n = S_DIM * S_DIM;
    for (int i = blockIdx.x * blockDim.x + threadIdx.x; i < n; i += gridDim.x * blockDim.x) {
        int nr = i / S_DIM, k = i % S_DIM;
        g_fc1e[i] = __float2half(fc1[(size_t)nr * 2 * S_DIM + k] +
                                 fc1[(size_t)nr * 2 * S_DIM + S_DIM + k]);
    }
}

__global__ void ww_interleave_kernel(const float* __restrict__ WW) {
    const size_t n = (size_t)4 * S_DIM * S_DIM;
    for (size_t i = (size_t)blockIdx.x * blockDim.x + threadIdx.x; i < n;
         i += (size_t)gridDim.x * blockDim.x) {
        size_t nr = i / S_DIM, k = i % S_DIM;
        size_t s = nr >> 2, gate = nr & 3;
        g_WWi[i] = __float2half(WW[(gate * S_DIM + s) * S_DIM + k]);
    }
}

__global__ void conv_h_kernel(const float* __restrict__ src, __half* __restrict__ dst, int n) {
    for (int i = blockIdx.x * blockDim.x + threadIdx.x; i < n; i += gridDim.x * blockDim.x)
        dst[i] = __float2half(src[i]);
}

// ---------------- host orchestration ----------------
extern "C" void kernel_launch(void* const* d_in, const int* in_sizes, int n_in,
                              void* d_out, int out_size) {
    const float* state  = (const float*)d_in[0];
    const float* act    = (const float*)d_in[1];
    const float* latent = (const float*)d_in[2];
    const float* fcW    = (const float*)d_in[3];
    const float* fcb    = (const float*)d_in[4];
    const float* fc1    = (const float*)d_in[5];
    const float* fc2    = (const float*)d_in[6];
    const float* WW     = (const float*)d_in[7];
    const float* rW     = (const float*)d_in[8];
    const float* rb     = (const float*)d_in[9];

    float* out     = (float*)d_out;
    float* preds   = out;
    float* rewards = out + PRED_ELEMS;

    __half *p_Wh, *p_Wap, *p_fc1e, *p_fc2, *p_WW, *p_al, *p_s0, *p_hn, *p_h, *p_x1, *p_x2;
    float *p_c, *p_ab, *p_part;
    cudaGetSymbolAddress((void**)&p_Wh,   g_Wh);
    cudaGetSymbolAddress((void**)&p_Wap,  g_Wap);
    cudaGetSymbolAddress((void**)&p_fc1e, g_fc1e);
    cudaGetSymbolAddress((void**)&p_fc2,  g_fc2);
    cudaGetSymbolAddress((void**)&p_WW,   g_WWi);
    cudaGetSymbolAddress((void**)&p_al,   g_al);
    cudaGetSymbolAddress((void**)&p_s0,   g_s0);
    cudaGetSymbolAddress((void**)&p_hn,   g_hn);
    cudaGetSymbolAddress((void**)&p_h,    g_h);
    cudaGetSymbolAddress((void**)&p_x1,   g_x1);
    cudaGetSymbolAddress((void**)&p_x2,   g_x2);
    cudaGetSymbolAddress((void**)&p_c,    g_c);
    cudaGetSymbolAddress((void**)&p_ab,   g_abias);
    cudaGetSymbolAddress((void**)&p_part, g_part);

    constexpr int SMEM_G = 3 * (128 + 128) * LDSH * (int)sizeof(__half);  // 208896
    cudaFuncSetAttribute((const void*)gemm_splitk<1, false>,
                         cudaFuncAttributeMaxDynamicSharedMemorySize, SMEM_G);
    cudaFuncSetAttribute((const void*)gemm_splitk<2, true>,
                         cudaFuncAttributeMaxDynamicSharedMemorySize, SMEM_G);
    cudaFuncSetAttribute((const void*)ww_gates_fused,
                         cudaFuncAttributeMaxDynamicSharedMemorySize, SMEM_G);

    const dim3 blk(256);
    const dim3 gS(S_DIM / 128, B_SZ / 128, 2);              // (16,2,2) = 64 CTAs
    const dim3 gAB(S_DIM / 128, T_STEPS * B_SZ / 128, 1);   // (16,64) abias GEMM
    const dim3 gW(4 * S_DIM / 128, B_SZ / 128);             // (64,2) = 128 CTAs

    // --- precompute; launch #4 = initial fc GEMM (profiled) ---
    pack_w_kernel<<<1024, 256>>>(fcW);                                 // 1
    al_init_kernel<<<1024, 256>>>(state, act, latent, rewards, rb);    // 2
    gemm_splitk<1, false><<<gAB, blk, SMEM_G>>>(                       // 3: abias
        p_al, p_Wap, nullptr, p_ab, nullptr, fcb, nullptr, S_DIM, ALP);
    gemm_splitk<2, true><<<gS, blk, SMEM_G>>>(                         // 4 (PROFILED)
        p_s0, p_Wh, p_part, p_c, p_h, nullptr, p_ab, S_DIM, S_DIM);
    fc1fold_kernel<<<1024, 256>>>(fc1);                                // 5
    ww_interleave_kernel<<<2048, 256>>>(WW);                           // 6
    conv_h_kernel<<<1024, 256>>>(fc2, p_fc2, S_DIM * S_DIM);           // 7

    for (int t = 0; t < T_STEPS; t++) {
        gemm_splitk<2, true><<<gS, blk, SMEM_G>>>(
            p_h, p_fc1e, p_part, nullptr, p_x1, nullptr, nullptr, S_DIM, S_DIM);
        gemm_splitk<2, true><<<gS, blk, SMEM_G>>>(
            p_x1, p_fc2, p_part, nullptr, p_x2, nullptr, nullptr, S_DIM, S_DIM);
        ww_gates_fused<<<gW, blk, SMEM_G>>>(p_x2, p_WW, p_c, p_hn, preds, rewards, rW, t);
        if (t < T_STEPS - 1)
            gemm_splitk<2, true><<<gS, blk, SMEM_G>>>(
                p_hn, p_Wh, p_part, nullptr, p_h, nullptr,
                p_ab + (size_t)t * B_SZ * S_DIM, S_DIM, S_DIM);
    }
}

// round 12
// speedup vs baseline: 1.1981x; 1.1981x over previous
#include <cuda_runtime.h>
#include <cuda_fp16.h>
#include <cstdint>
#include <math.h>

#define S_DIM 2048
#define A_DIM 64
#define P_DIM 128
#define B_SZ 256
#define T_STEPS 32
#define HS_DIM (S_DIM + A_DIM + P_DIM)   // 2240
#define ALP 256                          // padded K for act/latent GEMM
#define PRED_ELEMS ((size_t)T_STEPS * B_SZ * S_DIM)

// ---------------- device scratch (static, no allocations) ----------------
__device__ __half g_Wh   [S_DIM * S_DIM];
__device__ __half g_Wap  [S_DIM * ALP];
__device__ __half g_fc1e [S_DIM * S_DIM];
__device__ __half g_fc2  [S_DIM * S_DIM];
__device__ __half g_WWi  [4 * S_DIM * S_DIM];
__device__ __half g_al   [T_STEPS * B_SZ * ALP];
__device__ __half g_s0   [B_SZ * S_DIM];
__device__ float  g_abias[T_STEPS * B_SZ * S_DIM];
__device__ __half g_hn   [B_SZ * S_DIM];
__device__ __half g_h    [B_SZ * S_DIM];
__device__ __half g_x1   [B_SZ * S_DIM];
__device__ __half g_x2   [B_SZ * S_DIM];
__device__ float  g_c    [B_SZ * S_DIM];
__device__ float  g_part [2 * B_SZ * S_DIM];    // split-K partials (4MB)
__device__ int    g_tcnt [64];                  // per-tile arrival counters (mod-SPLIT)

// ---------------- helpers ----------------
__device__ __forceinline__ void cp16(void* sdst, const void* gsrc) {
    unsigned s = (unsigned)__cvta_generic_to_shared(sdst);
    asm volatile("cp.async.cg.shared.global [%0], [%1], 16;\n" :: "r"(s), "l"(gsrc));
}

__device__ __forceinline__ void ldsm_x4(uint32_t& r0, uint32_t& r1, uint32_t& r2, uint32_t& r3,
                                        const __half* p) {
    uint32_t a = (uint32_t)__cvta_generic_to_shared(p);
    asm volatile("ldmatrix.sync.aligned.m8n8.x4.shared.b16 {%0,%1,%2,%3}, [%4];\n"
                 : "=r"(r0), "=r"(r1), "=r"(r2), "=r"(r3) : "r"(a));
}

__device__ __forceinline__ void mma_f16(float c[4],
                                        uint32_t a0, uint32_t a1, uint32_t a2, uint32_t a3,
                                        uint32_t b0, uint32_t b1) {
    asm volatile(
        "mma.sync.aligned.m16n8k16.row.col.f32.f16.f16.f32 "
        "{%0,%1,%2,%3}, {%4,%5,%6,%7}, {%8,%9}, {%0,%1,%2,%3};\n"
        : "+f"(c[0]), "+f"(c[1]), "+f"(c[2]), "+f"(c[3])
        : "r"(a0), "r"(a1), "r"(a2), "r"(a3), "r"(b0), "r"(b1));
}

#define LDSH 136   // halves per smem row (128 data + 8 pad); 272 B

// ================= 64x128 HMMA GEMM (4 warps, warp tile 64x32), optional split-K =================
// A:[M,K], B:[N,K] fp16 row-major. blockIdx.z = K-slice. BK=128, 3 stages.
// SPLIT==1: direct epilogue. SPLIT>1: fp32 partial + counter; last CTA reduces
// in fixed z-order (deterministic) and applies bias/relu/conversion.
template<int SPLIT, bool RELU>
__global__ void __launch_bounds__(128, 1) gemm_splitk(
    const __half* __restrict__ A, const __half* __restrict__ Bm,
    float* __restrict__ part,
    float* __restrict__ outF, __half* __restrict__ outH,
    const float* __restrict__ colBias, const float* __restrict__ elemBias,
    int N, int K)
{
    constexpr int BM = 64, BN = 128, WR = 1, WC = 4;
    constexpr int NTH = 128;
    constexpr int NSTG = 3;
    constexpr int WM = BM / WR, WN = BN / WC;   // 64, 32
    constexpr int MF = WM / 16, NF = WN / 8;    // 4, 4
    constexpr int ROWS = BM + BN;               // 192
    constexpr int ITER = ROWS * 16 / NTH;       // 24

    extern __shared__ __half sm[];
    __shared__ int s_last;

    const int tid  = threadIdx.x;
    const int warp = tid >> 5;
    const int lane = tid & 31;
    const int wm = warp / WC;                   // 0
    const int wn = warp % WC;                   // 0..3
    const int g  = lane >> 2;
    const int tg = lane & 3;
    const int lr = lane & 7;
    const int lq = lane >> 3;

    const int z     = blockIdx.z;
    const int Ksl   = K / SPLIT;
    const int mbase = blockIdx.y * BM;
    const int nbase = blockIdx.x * BN;
    const __half* Ab = A  + (size_t)mbase * K + (size_t)z * Ksl;
    const __half* Bb = Bm + (size_t)nbase * K + (size_t)z * Ksl;
    const int nk = Ksl >> 7;

    float acc[MF][NF][4];
#pragma unroll
    for (int i = 0; i < MF; i++)
#pragma unroll
        for (int j = 0; j < NF; j++)
#pragma unroll
            for (int e = 0; e < 4; e++) acc[i][j][e] = 0.f;

    auto load_stage = [&](int st, int kb) {
        const int k0 = kb * 128;
        __half* Ao = sm + (size_t)st * ROWS * LDSH;
        __half* Bo = Ao + (size_t)BM * LDSH;
#pragma unroll
        for (int i = 0; i < ITER; i++) {
            int id  = tid + i * NTH;
            int row = id >> 4;
            int kc  = (id & 15) * 8;
            if (row < BM)
                cp16(Ao + (size_t)row * LDSH + kc, Ab + (size_t)row * K + k0 + kc);
            else
                cp16(Bo + (size_t)(row - BM) * LDSH + kc,
                     Bb + (size_t)(row - BM) * K + k0 + kc);
        }
        asm volatile("cp.async.commit_group;\n" ::: "memory");
    };

    if (0 < nk) load_stage(0, 0);
    if (1 < nk) load_stage(1, 1);

    uint32_t a[2][MF][4];
    uint32_t b[2][NF][2];

    for (int kb = 0; kb < nk; kb++) {
        const int rem = nk - 1 - kb;
        const int allow = rem < NSTG - 2 ? rem : NSTG - 2;
        if (allow >= 1) asm volatile("cp.async.wait_group 1;\n" ::: "memory");
        else            asm volatile("cp.async.wait_group 0;\n" ::: "memory");
        __syncthreads();

        if (kb + 2 < nk) load_stage((kb + 2) % NSTG, kb + 2);

        const int st = kb % NSTG;
        const __half* Abase = sm + (size_t)st * ROWS * LDSH;
        const __half* Bbase = Abase + (size_t)BM * LDSH;

        auto load_frag = [&](int buf, int k0) {
#pragma unroll
            for (int mf = 0; mf < MF; mf++) {
                int row = wm * WM + mf * 16 + (lq & 1) * 8 + lr;
                int col = k0 + (lq >> 1) * 8;
                ldsm_x4(a[buf][mf][0], a[buf][mf][1], a[buf][mf][2], a[buf][mf][3],
                        Abase + (size_t)row * LDSH + col);
            }
#pragma unroll
            for (int np = 0; np < NF / 2; np++) {
                int row = wn * WN + np * 16 + (lq >> 1) * 8 + lr;
                int col = k0 + (lq & 1) * 8;
                uint32_t r0, r1, r2, r3;
                ldsm_x4(r0, r1, r2, r3, Bbase + (size_t)row * LDSH + col);
                b[buf][2 * np][0] = r0; b[buf][2 * np][1] = r1;
                b[buf][2 * np + 1][0] = r2; b[buf][2 * np + 1][1] = r3;
            }
        };

        load_frag(0, 0);
#pragma unroll
        for (int ks = 0; ks < 8; ks++) {
            const int cur = ks & 1;
            if (ks < 7) load_frag(cur ^ 1, (ks + 1) * 16);
#pragma unroll
            for (int mf = 0; mf < MF; mf++)
#pragma unroll
                for (int nf = 0; nf < NF; nf++)
                    mma_f16(acc[mf][nf], a[cur][mf][0], a[cur][mf][1],
                            a[cur][mf][2], a[cur][mf][3],
                            b[cur][nf][0], b[cur][nf][1]);
        }
    }

    if (SPLIT == 1) {
#pragma unroll
        for (int nf = 0; nf < NF; nf++) {
            int col = nbase + wn * WN + nf * 8 + 2 * tg;
            float cb0 = colBias ? colBias[col]     : 0.f;
            float cb1 = colBias ? colBias[col + 1] : 0.f;
#pragma unroll
            for (int mf = 0; mf < MF; mf++) {
                int row = mbase + wm * WM + mf * 16 + g;
                size_t o0 = (size_t)row * N + col;
                size_t o1 = (size_t)(row + 8) * N + col;
                float v00 = acc[mf][nf][0] + cb0;
                float v01 = acc[mf][nf][1] + cb1;
                float v10 = acc[mf][nf][2] + cb0;
                float v11 = acc[mf][nf][3] + cb1;
                if (RELU) {
                    v00 = fmaxf(v00, 0.f); v01 = fmaxf(v01, 0.f);
                    v10 = fmaxf(v10, 0.f); v11 = fmaxf(v11, 0.f);
                }
                if (outF) {
                    *(float2*)(outF + o0) = make_float2(v00, v01);
                    *(float2*)(outF + o1) = make_float2(v10, v11);
                }
                if (outH) {
                    *(__half2*)(outH + o0) = __floats2half2_rn(v00, v01);
                    *(__half2*)(outH + o1) = __floats2half2_rn(v10, v11);
                }
            }
        }
        return;
    }

    // split-K: store fp32 partial slice
    const size_t MN = (size_t)B_SZ * N;
    float* myp = part + (size_t)z * MN;
#pragma unroll
    for (int nf = 0; nf < NF; nf++) {
        int col = nbase + wn * WN + nf * 8 + 2 * tg;
#pragma unroll
        for (int mf = 0; mf < MF; mf++) {
            int row = mbase + wm * WM + mf * 16 + g;
            size_t o0 = (size_t)row * N + col;
            size_t o1 = (size_t)(row + 8) * N + col;
            *(float2*)(myp + o0) = make_float2(acc[mf][nf][0], acc[mf][nf][1]);
            *(float2*)(myp + o1) = make_float2(acc[mf][nf][2], acc[mf][nf][3]);
        }
    }
    __threadfence();
    __syncthreads();
    if (tid == 0) {
        int tile = blockIdx.y * gridDim.x + blockIdx.x;
        int v = atomicAdd(&g_tcnt[tile], 1) + 1;
        s_last = ((v % SPLIT) == 0) ? 1 : 0;
    }
    __syncthreads();
    if (!s_last) return;
    __threadfence();

    // last CTA: reduce in fixed z-order + epilogue
#pragma unroll
    for (int nf = 0; nf < NF; nf++) {
        int col = nbase + wn * WN + nf * 8 + 2 * tg;
        float cb0 = colBias ? colBias[col]     : 0.f;
        float cb1 = colBias ? colBias[col + 1] : 0.f;
#pragma unroll
        for (int mf = 0; mf < MF; mf++) {
            int row = mbase + wm * WM + mf * 16 + g;
            size_t o0 = (size_t)row * N + col;
            size_t o1 = (size_t)(row + 8) * N + col;
            float v00 = 0.f, v01 = 0.f, v10 = 0.f, v11 = 0.f;
#pragma unroll
            for (int zz = 0; zz < SPLIT; zz++) {
                if (zz == z) {
                    v00 += acc[mf][nf][0]; v01 += acc[mf][nf][1];
                    v10 += acc[mf][nf][2]; v11 += acc[mf][nf][3];
                } else {
                    float2 p0 = __ldcg((const float2*)(part + (size_t)zz * MN + o0));
                    float2 p1 = __ldcg((const float2*)(part + (size_t)zz * MN + o1));
                    v00 += p0.x; v01 += p0.y; v10 += p1.x; v11 += p1.y;
                }
            }
            if (elemBias) {
                float2 ea = *(const float2*)(elemBias + o0);
                float2 eb = *(const float2*)(elemBias + o1);
                v00 += ea.x; v01 += ea.y; v10 += eb.x; v11 += eb.y;
            }
            v00 += cb0; v01 += cb1; v10 += cb0; v11 += cb1;
            if (RELU) {
                v00 = fmaxf(v00, 0.f); v01 = fmaxf(v01, 0.f);
                v10 = fmaxf(v10, 0.f); v11 = fmaxf(v11, 0.f);
            }
            if (outF) {
                *(float2*)(outF + o0) = make_float2(v00, v01);
                *(float2*)(outF + o1) = make_float2(v10, v11);
            }
            if (outH) {
                *(__half2*)(outH + o0) = __floats2half2_rn(v00, v01);
                *(__half2*)(outH + o1) = __floats2half2_rn(v10, v11);
            }
        }
    }
}

// ================= WW GEMM + gates (256 threads, warp tile 64x32) =================
__global__ void __launch_bounds__(256, 1) ww_gates_fused(
    const __half* __restrict__ A, const __half* __restrict__ Bm,
    float* __restrict__ cell, __half* __restrict__ hn,
    float* __restrict__ preds, float* __restrict__ rewards,
    const float* __restrict__ rW, int t)
{
    constexpr int BM = 128, BN = 128, WR = 2, WC = 4;
    constexpr int NTH = 256;
    constexpr int NSTG = 3;
    constexpr int WM = BM / WR, WN = BN / WC;   // 64, 32
    constexpr int MF = WM / 16, NF = WN / 8;    // 4, 4
    constexpr int ROWS = BM + BN;
    constexpr int ITER = ROWS * 16 / NTH;       // 16
    constexpr int K = S_DIM;
    constexpr int nk = K / 128;                 // 16
    constexpr int EST = 132;

    extern __shared__ __half sm[];

    const int tid  = threadIdx.x;
    const int warp = tid >> 5;
    const int lane = tid & 31;
    const int wm = warp / WC;
    const int wn = warp % WC;
    const int g  = lane >> 2;
    const int tg = lane & 3;
    const int lr = lane & 7;
    const int lq = lane >> 3;

    const int mbase = blockIdx.y * BM;
    const int nbase = blockIdx.x * BN;
    const __half* Ab = A  + (size_t)mbase * K;
    const __half* Bb = Bm + (size_t)nbase * K;

    float acc[MF][NF][4];
#pragma unroll
    for (int i = 0; i < MF; i++)
#pragma unroll
        for (int j = 0; j < NF; j++)
#pragma unroll
            for (int e = 0; e < 4; e++) acc[i][j][e] = 0.f;

    auto load_stage = [&](int st, int kb) {
        const int k0 = kb * 128;
        __half* Ao = sm + (size_t)st * ROWS * LDSH;
        __half* Bo = Ao + (size_t)BM * LDSH;
#pragma unroll
        for (int i = 0; i < ITER; i++) {
            int id  = tid + i * NTH;
            int row = id >> 4;
            int kc  = (id & 15) * 8;
            if (row < BM)
                cp16(Ao + (size_t)row * LDSH + kc, Ab + (size_t)row * K + k0 + kc);
            else
                cp16(Bo + (size_t)(row - BM) * LDSH + kc,
                     Bb + (size_t)(row - BM) * K + k0 + kc);
        }
        asm volatile("cp.async.commit_group;\n" ::: "memory");
    };

    load_stage(0, 0);
    load_stage(1, 1);

    uint32_t a[2][MF][4];
    uint32_t b[2][NF][2];

    for (int kb = 0; kb < nk; kb++) {
        const int rem = nk - 1 - kb;
        const int allow = rem < NSTG - 2 ? rem : NSTG - 2;
        if (allow >= 1) asm volatile("cp.async.wait_group 1;\n" ::: "memory");
        else            asm volatile("cp.async.wait_group 0;\n" ::: "memory");
        __syncthreads();

        if (kb + 2 < nk) load_stage((kb + 2) % NSTG, kb + 2);

        const int st = kb % NSTG;
        const __half* Abase = sm + (size_t)st * ROWS * LDSH;
        const __half* Bbase = Abase + (size_t)BM * LDSH;

        auto load_frag = [&](int buf, int k0) {
#pragma unroll
            for (int mf = 0; mf < MF; mf++) {
                int row = wm * WM + mf * 16 + (lq & 1) * 8 + lr;
                int col = k0 + (lq >> 1) * 8;
                ldsm_x4(a[buf][mf][0], a[buf][mf][1], a[buf][mf][2], a[buf][mf][3],
                        Abase + (size_t)row * LDSH + col);
            }
#pragma unroll
            for (int np = 0; np < NF / 2; np++) {
                int row = wn * WN + np * 16 + (lq >> 1) * 8 + lr;
                int col = k0 + (lq & 1) * 8;
                uint32_t r0, r1, r2, r3;
                ldsm_x4(r0, r1, r2, r3, Bbase + (size_t)row * LDSH + col);
                b[buf][2 * np][0] = r0; b[buf][2 * np][1] = r1;
                b[buf][2 * np + 1][0] = r2; b[buf][2 * np + 1][1] = r3;
            }
        };

        load_frag(0, 0);
#pragma unroll
        for (int ks = 0; ks < 8; ks++) {
            const int cur = ks & 1;
            if (ks < 7) load_frag(cur ^ 1, (ks + 1) * 16);
#pragma unroll
            for (int mf = 0; mf < MF; mf++)
#pragma unroll
                for (int nf = 0; nf < NF; nf++)
                    mma_f16(acc[mf][nf], a[cur][mf][0], a[cur][mf][1],
                            a[cur][mf][2], a[cur][mf][3],
                            b[cur][nf][0], b[cur][nf][1]);
        }
    }

    __syncthreads();
    float* smf = (float*)sm;
#pragma unroll
    for (int nf = 0; nf < NF; nf++) {
        int col = wn * WN + nf * 8 + 2 * tg;
#pragma unroll
        for (int mf = 0; mf < MF; mf++) {
            int row = wm * WM + mf * 16 + g;
            *(float2*)&smf[(size_t)row * EST + col]       = make_float2(acc[mf][nf][0], acc[mf][nf][1]);
            *(float2*)&smf[(size_t)(row + 8) * EST + col] = make_float2(acc[mf][nf][2], acc[mf][nf][3]);
        }
    }
    __syncthreads();

    const int b_local = tid >> 1;
    const int bb = mbase + b_local;
    float rsum = 0.f;
#pragma unroll
    for (int i = 0; i < 16; i++) {
        int s_local = (tid & 1) * 16 + i;
        float4 q = *(float4*)&smf[(size_t)b_local * EST + 4 * s_local];
        float ci = fmaxf(q.x, 0.f);
        float cf = fmaxf(q.y, 0.f);
        float co = fmaxf(q.z, 0.f);
        float cg = fmaxf(q.w, 0.f);
        float ig = 1.f / (1.f + __expf(-ci));
        float fg = 1.f / (1.f + __expf(-cf));
        float og = 1.f / (1.f + __expf(-co));
        float gg = tanhf(cg);
        int s_glob = (nbase >> 2) + s_local;
        size_t cidx = (size_t)bb * S_DIM + s_glob;
        float cn = fg * cell[cidx] + ig * gg;
        float hnv = og * tanhf(cn);
        cell[cidx] = cn;
        preds[((size_t)t * B_SZ + bb) * S_DIM + s_glob] = hnv;
        hn[(size_t)bb * S_DIM + s_glob] = __float2half(hnv);
        rsum += hnv * rW[s_glob];
    }
    rsum += __shfl_xor_sync(0xffffffffu, rsum, 1);
    if (!(tid & 1)) atomicAdd(&rewards[t * B_SZ + bb], rsum);
}

// ---------------- precompute kernels ----------------
__global__ void pack_w_kernel(const float* __restrict__ fcW) {
    const int n1 = S_DIM * S_DIM;
    for (int i = blockIdx.x * blockDim.x + threadIdx.x; i < n1; i += gridDim.x * blockDim.x) {
        int nr = i / S_DIM, k = i % S_DIM;
        g_Wh[i] = __float2half(fcW[(size_t)nr * HS_DIM + k]);
    }
    const int n2 = S_DIM * ALP;
    for (int i = blockIdx.x * blockDim.x + threadIdx.x; i < n2; i += gridDim.x * blockDim.x) {
        int nr = i / ALP, c = i % ALP;
        float v = (c < A_DIM + P_DIM) ? fcW[(size_t)nr * HS_DIM + S_DIM + c] : 0.f;
        g_Wap[i] = __float2half(v);
    }
}

__global__ void al_init_kernel(const float* __restrict__ state,
                               const float* __restrict__ act,
                               const float* __restrict__ latent,
                               float* __restrict__ rewards,
                               const float* __restrict__ rb) {
    const int n1 = T_STEPS * B_SZ * ALP;
    for (int i = blockIdx.x * blockDim.x + threadIdx.x; i < n1; i += gridDim.x * blockDim.x) {
        int r = i / ALP, c = i % ALP;
        int t = r / B_SZ, b = r % B_SZ;
        float v;
        if (c < A_DIM)              v = act[((size_t)b * T_STEPS + t) * A_DIM + c];
        else if (c < A_DIM + P_DIM) v = latent[(size_t)b * P_DIM + (c - A_DIM)];
        else                        v = 0.f;
        g_al[i] = __float2half(v);
    }
    const int n2 = B_SZ * S_DIM;
    for (int i = blockIdx.x * blockDim.x + threadIdx.x; i < n2; i += gridDim.x * blockDim.x)
        g_s0[i] = __float2half(state[i]);
    for (int i = blockIdx.x * blockDim.x + threadIdx.x; i < T_STEPS * B_SZ;
         i += gridDim.x * blockDim.x)
        rewards[i] = rb[0];
}

__global__ void fc1fold_kernel(const float* __restrict__ fc1) {
    const int n = S_DIM * S_DIM;
    for (int i = blockIdx.x * blockDim.x + threadIdx.x; i < n; i += gridDim.x * blockDim.x) {
        int nr = i / S_DIM, k = i % S_DIM;
        g_fc1e[i] = __float2half(fc1[(size_t)nr * 2 * S_DIM + k] +
                                 fc1[(size_t)nr * 2 * S_DIM + S_DIM + k]);
    }
}

__global__ void ww_interleave_kernel(const float* __restrict__ WW) {
    const size_t n = (size_t)4 * S_DIM * S_DIM;
    for (size_t i = (size_t)blockIdx.x * blockDim.x + threadIdx.x; i < n;
         i += (size_t)gridDim.x * blockDim.x) {
        size_t nr = i / S_DIM, k = i % S_DIM;
        size_t s = nr >> 2, gate = nr & 3;
        g_WWi[i] = __float2half(WW[(gate * S_DIM + s) * S_DIM + k]);
    }
}

__global__ void conv_h_kernel(const float* __restrict__ src, __half* __restrict__ dst, int n) {
    for (int i = blockIdx.x * blockDim.x + threadIdx.x; i < n; i += gridDim.x * blockDim.x)
        dst[i] = __float2half(src[i]);
}

// ---------------- host orchestration ----------------
extern "C" void kernel_launch(void* const* d_in, const int* in_sizes, int n_in,
                              void* d_out, int out_size) {
    const float* state  = (const float*)d_in[0];
    const float* act    = (const float*)d_in[1];
    const float* latent = (const float*)d_in[2];
    const float* fcW    = (const float*)d_in[3];
    const float* fcb    = (const float*)d_in[4];
    const float* fc1    = (const float*)d_in[5];
    const float* fc2    = (const float*)d_in[6];
    const float* WW     = (const float*)d_in[7];
    const float* rW     = (const float*)d_in[8];
    const float* rb     = (const float*)d_in[9];

    float* out     = (float*)d_out;
    float* preds   = out;
    float* rewards = out + PRED_ELEMS;

    __half *p_Wh, *p_Wap, *p_fc1e, *p_fc2, *p_WW, *p_al, *p_s0, *p_hn, *p_h, *p_x1, *p_x2;
    float *p_c, *p_ab, *p_part;
    cudaGetSymbolAddress((void**)&p_Wh,   g_Wh);
    cudaGetSymbolAddress((void**)&p_Wap,  g_Wap);
    cudaGetSymbolAddress((void**)&p_fc1e, g_fc1e);
    cudaGetSymbolAddress((void**)&p_fc2,  g_fc2);
    cudaGetSymbolAddress((void**)&p_WW,   g_WWi);
    cudaGetSymbolAddress((void**)&p_al,   g_al);
    cudaGetSymbolAddress((void**)&p_s0,   g_s0);
    cudaGetSymbolAddress((void**)&p_hn,   g_hn);
    cudaGetSymbolAddress((void**)&p_h,    g_h);
    cudaGetSymbolAddress((void**)&p_x1,   g_x1);
    cudaGetSymbolAddress((void**)&p_x2,   g_x2);
    cudaGetSymbolAddress((void**)&p_c,    g_c);
    cudaGetSymbolAddress((void**)&p_ab,   g_abias);
    cudaGetSymbolAddress((void**)&p_part, g_part);

    constexpr int SMEM_S = 3 * (64 + 128)  * LDSH * (int)sizeof(__half);  // 156672
    constexpr int SMEM_W = 3 * (128 + 128) * LDSH * (int)sizeof(__half);  // 208896
    cudaFuncSetAttribute((const void*)gemm_splitk<1, false>,
                         cudaFuncAttributeMaxDynamicSharedMemorySize, SMEM_S);
    cudaFuncSetAttribute((const void*)gemm_splitk<2, true>,
                         cudaFuncAttributeMaxDynamicSharedMemorySize, SMEM_S);
    cudaFuncSetAttribute((const void*)ww_gates_fused,
                         cudaFuncAttributeMaxDynamicSharedMemorySize, SMEM_W);

    const dim3 blkS(128), blkW(256);
    const dim3 gS(S_DIM / 128, B_SZ / 64, 2);               // (16,4,2) = 128 CTAs
    const dim3 gAB(S_DIM / 128, T_STEPS * B_SZ / 64, 1);    // (16,128) abias GEMM
    const dim3 gW(4 * S_DIM / 128, B_SZ / 128);             // (64,2) = 128 CTAs

    // --- precompute; launch #4 = initial fc GEMM (profiled) ---
    pack_w_kernel<<<1024, 256>>>(fcW);                                 // 1
    al_init_kernel<<<1024, 256>>>(state, act, latent, rewards, rb);    // 2
    gemm_splitk<1, false><<<gAB, blkS, SMEM_S>>>(                      // 3: abias
        p_al, p_Wap, nullptr, p_ab, nullptr, fcb, nullptr, S_DIM, ALP);
    gemm_splitk<2, true><<<gS, blkS, SMEM_S>>>(                        // 4 (PROFILED)
        p_s0, p_Wh, p_part, p_c, p_h, nullptr, p_ab, S_DIM, S_DIM);
    fc1fold_kernel<<<1024, 256>>>(fc1);                                // 5
    ww_interleave_kernel<<<2048, 256>>>(WW);                           // 6
    conv_h_kernel<<<1024, 256>>>(fc2, p_fc2, S_DIM * S_DIM);           // 7

    for (int t = 0; t < T_STEPS; t++) {
        gemm_splitk<2, true><<<gS, blkS, SMEM_S>>>(
            p_h, p_fc1e, p_part, nullptr, p_x1, nullptr, nullptr, S_DIM, S_DIM);
        gemm_splitk<2, true><<<gS, blkS, SMEM_S>>>(
            p_x1, p_fc2, p_part, nullptr, p_x2, nullptr, nullptr, S_DIM, S_DIM);
        ww_gates_fused<<<gW, blkW, SMEM_W>>>(p_x2, p_WW, p_c, p_hn, preds, rewards, rW, t);
        if (t < T_STEPS - 1)
            gemm_splitk<2, true><<<gS, blkS, SMEM_S>>>(
                p_hn, p_Wh, p_part, nullptr, p_h, nullptr,
                p_ab + (size_t)t * B_SZ * S_DIM, S_DIM, S_DIM);
    }
}

// round 13
// speedup vs baseline: 1.3050x; 1.0892x over previous
#include <cuda_runtime.h>
#include <cuda_fp16.h>
#include <cstdint>
#include <math.h>

#define S_DIM 2048
#define A_DIM 64
#define P_DIM 128
#define B_SZ 256
#define T_STEPS 32
#define HS_DIM (S_DIM + A_DIM + P_DIM)   // 2240
#define ALP 256                          // padded K for act/latent GEMM
#define PRED_ELEMS ((size_t)T_STEPS * B_SZ * S_DIM)

// ---------------- device scratch (static, no allocations) ----------------
__device__ __half g_Wh   [S_DIM * S_DIM];
__device__ __half g_Wap  [S_DIM * ALP];
__device__ __half g_fc1e [S_DIM * S_DIM];
__device__ __half g_fc2  [S_DIM * S_DIM];
__device__ __half g_WWi  [4 * S_DIM * S_DIM];
__device__ __half g_al   [T_STEPS * B_SZ * ALP];
__device__ __half g_s0   [B_SZ * S_DIM];
__device__ float  g_abias[T_STEPS * B_SZ * S_DIM];
__device__ __half g_hn   [B_SZ * S_DIM];
__device__ __half g_h    [B_SZ * S_DIM];
__device__ __half g_x1   [B_SZ * S_DIM];
__device__ __half g_x2   [B_SZ * S_DIM];
__device__ float  g_c    [B_SZ * S_DIM];

// ---------------- helpers ----------------
__device__ __forceinline__ void cp16(void* sdst, const void* gsrc) {
    unsigned s = (unsigned)__cvta_generic_to_shared(sdst);
    asm volatile("cp.async.cg.shared.global [%0], [%1], 16;\n" :: "r"(s), "l"(gsrc));
}

__device__ __forceinline__ void ldsm_x4(uint32_t& r0, uint32_t& r1, uint32_t& r2, uint32_t& r3,
                                        const __half* p) {
    uint32_t a = (uint32_t)__cvta_generic_to_shared(p);
    asm volatile("ldmatrix.sync.aligned.m8n8.x4.shared.b16 {%0,%1,%2,%3}, [%4];\n"
                 : "=r"(r0), "=r"(r1), "=r"(r2), "=r"(r3) : "r"(a));
}

__device__ __forceinline__ void mma_f16(float c[4],
                                        uint32_t a0, uint32_t a1, uint32_t a2, uint32_t a3,
                                        uint32_t b0, uint32_t b1) {
    asm volatile(
        "mma.sync.aligned.m16n8k16.row.col.f32.f16.f16.f32 "
        "{%0,%1,%2,%3}, {%4,%5,%6,%7}, {%8,%9}, {%0,%1,%2,%3};\n"
        : "+f"(c[0]), "+f"(c[1]), "+f"(c[2]), "+f"(c[3])
        : "r"(a0), "r"(a1), "r"(a2), "r"(a3), "r"(b0), "r"(b1));
}

__device__ __forceinline__ float fast_sigmoid(float x) {
    return __fdividef(1.f, 1.f + __expf(-x));
}
__device__ __forceinline__ float fast_tanh(float x) {
    return __fdividef(2.f, 1.f + __expf(-2.f * x)) - 1.f;
}

#define LDSH 136   // halves per smem row (128 data + 8 pad); 272 B

// ================= generic fp16 HMMA GEMM =================
// out = [relu](A @ B^T + colBias + elemBias). A:[M,K], B:[N,K] fp16 row-major.
// Register double-buffered fragments; BK=128; NSTG-stage cp.async pipeline.
template<int BM, int BN, int WR, int WC, int NSTG, bool RELU>
__global__ void __launch_bounds__(256) gemm_hmma(
    const __half* __restrict__ A, const __half* __restrict__ Bm,
    float* __restrict__ outF, __half* __restrict__ outH,
    const float* __restrict__ colBias, const float* __restrict__ elemBias,
    int N, int K)
{
    constexpr int NTH = WR * WC * 32;
    constexpr int WM = BM / WR, WN = BN / WC;
    constexpr int MF = WM / 16, NF = WN / 8;
    constexpr int ROWS = BM + BN;
    constexpr int ITER = ROWS * 16 / NTH;

    extern __shared__ __half sm[];

    const int tid  = threadIdx.x;
    const int warp = tid >> 5;
    const int lane = tid & 31;
    const int wm = warp / WC;
    const int wn = warp % WC;
    const int g  = lane >> 2;
    const int tg = lane & 3;
    const int lr = lane & 7;
    const int lq = lane >> 3;

    const int mbase = blockIdx.y * BM;
    const int nbase = blockIdx.x * BN;
    const __half* Ab = A  + (size_t)mbase * K;
    const __half* Bb = Bm + (size_t)nbase * K;
    const int nk = K >> 7;

    float acc[MF][NF][4];
#pragma unroll
    for (int i = 0; i < MF; i++)
#pragma unroll
        for (int j = 0; j < NF; j++)
#pragma unroll
            for (int e = 0; e < 4; e++) acc[i][j][e] = 0.f;

    auto load_stage = [&](int st, int kb) {
        const int k0 = kb * 128;
        __half* Ao = sm + (size_t)st * ROWS * LDSH;
        __half* Bo = Ao + (size_t)BM * LDSH;
#pragma unroll
        for (int i = 0; i < ITER; i++) {
            int id  = tid + i * NTH;
            int row = id >> 4;
            int kc  = (id & 15) * 8;
            if (row < BM)
                cp16(Ao + (size_t)row * LDSH + kc, Ab + (size_t)row * K + k0 + kc);
            else
                cp16(Bo + (size_t)(row - BM) * LDSH + kc,
                     Bb + (size_t)(row - BM) * K + k0 + kc);
        }
        asm volatile("cp.async.commit_group;\n" ::: "memory");
    };

#pragma unroll
    for (int s = 0; s < NSTG - 1; s++)
        if (s < nk) load_stage(s, s);

    uint32_t a[2][MF][4];
    uint32_t b[2][NF][2];

    for (int kb = 0; kb < nk; kb++) {
        const int rem = nk - 1 - kb;
        const int allow = rem < NSTG - 2 ? rem : NSTG - 2;
        if (allow >= 2)      asm volatile("cp.async.wait_group 2;\n" ::: "memory");
        else if (allow == 1) asm volatile("cp.async.wait_group 1;\n" ::: "memory");
        else                 asm volatile("cp.async.wait_group 0;\n" ::: "memory");
        __syncthreads();

        if (kb + NSTG - 1 < nk) load_stage((kb + NSTG - 1) % NSTG, kb + NSTG - 1);

        const int st = kb % NSTG;
        const __half* Abase = sm + (size_t)st * ROWS * LDSH;
        const __half* Bbase = Abase + (size_t)BM * LDSH;

        auto load_frag = [&](int buf, int k0) {
#pragma unroll
            for (int mf = 0; mf < MF; mf++) {
                int row = wm * WM + mf * 16 + (lq & 1) * 8 + lr;
                int col = k0 + (lq >> 1) * 8;
                ldsm_x4(a[buf][mf][0], a[buf][mf][1], a[buf][mf][2], a[buf][mf][3],
                        Abase + (size_t)row * LDSH + col);
            }
#pragma unroll
            for (int np = 0; np < NF / 2; np++) {
                int row = wn * WN + np * 16 + (lq >> 1) * 8 + lr;
                int col = k0 + (lq & 1) * 8;
                uint32_t r0, r1, r2, r3;
                ldsm_x4(r0, r1, r2, r3, Bbase + (size_t)row * LDSH + col);
                b[buf][2 * np][0] = r0; b[buf][2 * np][1] = r1;
                b[buf][2 * np + 1][0] = r2; b[buf][2 * np + 1][1] = r3;
            }
        };

        load_frag(0, 0);
#pragma unroll
        for (int ks = 0; ks < 8; ks++) {
            const int cur = ks & 1;
            if (ks < 7) load_frag(cur ^ 1, (ks + 1) * 16);
#pragma unroll
            for (int mf = 0; mf < MF; mf++)
#pragma unroll
                for (int nf = 0; nf < NF; nf++)
                    mma_f16(acc[mf][nf], a[cur][mf][0], a[cur][mf][1],
                            a[cur][mf][2], a[cur][mf][3],
                            b[cur][nf][0], b[cur][nf][1]);
        }
    }

    // epilogue
#pragma unroll
    for (int nf = 0; nf < NF; nf++) {
        int col = nbase + wn * WN + nf * 8 + 2 * tg;
        float cb0 = colBias ? colBias[col]     : 0.f;
        float cb1 = colBias ? colBias[col + 1] : 0.f;
#pragma unroll
        for (int mf = 0; mf < MF; mf++) {
            int row = mbase + wm * WM + mf * 16 + g;
            size_t o0 = (size_t)row * N + col;
            size_t o1 = (size_t)(row + 8) * N + col;
            float e00 = 0.f, e01 = 0.f, e10 = 0.f, e11 = 0.f;
            if (elemBias) {
                // abias elements are read exactly once ever: stream (evict-first)
                float2 ea = __ldcs((const float2*)(elemBias + o0));
                float2 eb = __ldcs((const float2*)(elemBias + o1));
                e00 = ea.x; e01 = ea.y; e10 = eb.x; e11 = eb.y;
            }
            float v00 = acc[mf][nf][0] + cb0 + e00;
            float v01 = acc[mf][nf][1] + cb1 + e01;
            float v10 = acc[mf][nf][2] + cb0 + e10;
            float v11 = acc[mf][nf][3] + cb1 + e11;
            if (RELU) {
                v00 = fmaxf(v00, 0.f); v01 = fmaxf(v01, 0.f);
                v10 = fmaxf(v10, 0.f); v11 = fmaxf(v11, 0.f);
            }
            if (outF) {
                *(float2*)(outF + o0) = make_float2(v00, v01);
                *(float2*)(outF + o1) = make_float2(v10, v11);
            }
            if (outH) {
                *(__half2*)(outH + o0) = __floats2half2_rn(v00, v01);
                *(__half2*)(outH + o1) = __floats2half2_rn(v10, v11);
            }
        }
    }
}

// ================= WW GEMM fused with LSTM gates / reward =================
__global__ void __launch_bounds__(256) ww_gates_fused(
    const __half* __restrict__ A,       // x2 [256, 2048]
    const __half* __restrict__ Bm,      // WW interleaved [8192, 2048]
    float* __restrict__ cell,
    __half* __restrict__ hn,
    float* __restrict__ preds,
    float* __restrict__ rewards,
    const float* __restrict__ rW, int t)
{
    constexpr int BM = 128, BN = 128, WR = 2, WC = 4;
    constexpr int NTH = 256;
    constexpr int NSTG = 3;
    constexpr int WM = BM / WR, WN = BN / WC;   // 64, 32
    constexpr int MF = WM / 16, NF = WN / 8;    // 4, 4
    constexpr int ROWS = BM + BN;
    constexpr int ITER = ROWS * 16 / NTH;       // 16
    constexpr int K = S_DIM;
    constexpr int nk = K / 128;                 // 16
    constexpr int EST = 132;

    extern __shared__ __half sm[];

    const int tid  = threadIdx.x;
    const int warp = tid >> 5;
    const int lane = tid & 31;
    const int wm = warp / WC;
    const int wn = warp % WC;
    const int g  = lane >> 2;
    const int tg = lane & 3;
    const int lr = lane & 7;
    const int lq = lane >> 3;

    const int mbase = blockIdx.y * BM;
    const int nbase = blockIdx.x * BN;
    const __half* Ab = A  + (size_t)mbase * K;
    const __half* Bb = Bm + (size_t)nbase * K;

    float acc[MF][NF][4];
#pragma unroll
    for (int i = 0; i < MF; i++)
#pragma unroll
        for (int j = 0; j < NF; j++)
#pragma unroll
            for (int e = 0; e < 4; e++) acc[i][j][e] = 0.f;

    auto load_stage = [&](int st, int kb) {
        const int k0 = kb * 128;
        __half* Ao = sm + (size_t)st * ROWS * LDSH;
        __half* Bo = Ao + (size_t)BM * LDSH;
#pragma unroll
        for (int i = 0; i < ITER; i++) {
            int id  = tid + i * NTH;
            int row = id >> 4;
            int kc  = (id & 15) * 8;
            if (row < BM)
                cp16(Ao + (size_t)row * LDSH + kc, Ab + (size_t)row * K + k0 + kc);
            else
                cp16(Bo + (size_t)(row - BM) * LDSH + kc,
                     Bb + (size_t)(row - BM) * K + k0 + kc);
        }
        asm volatile("cp.async.commit_group;\n" ::: "memory");
    };

    load_stage(0, 0);
    load_stage(1, 1);

    uint32_t a[2][MF][4];
    uint32_t b[2][NF][2];

    for (int kb = 0; kb < nk; kb++) {
        const int rem = nk - 1 - kb;
        const int allow = rem < NSTG - 2 ? rem : NSTG - 2;
        if (allow >= 1) asm volatile("cp.async.wait_group 1;\n" ::: "memory");
        else            asm volatile("cp.async.wait_group 0;\n" ::: "memory");
        __syncthreads();

        if (kb + 2 < nk) load_stage((kb + 2) % NSTG, kb + 2);

        const int st = kb % NSTG;
        const __half* Abase = sm + (size_t)st * ROWS * LDSH;
        const __half* Bbase = Abase + (size_t)BM * LDSH;

        auto load_frag = [&](int buf, int k0) {
#pragma unroll
            for (int mf = 0; mf < MF; mf++) {
                int row = wm * WM + mf * 16 + (lq & 1) * 8 + lr;
                int col = k0 + (lq >> 1) * 8;
                ldsm_x4(a[buf][mf][0], a[buf][mf][1], a[buf][mf][2], a[buf][mf][3],
                        Abase + (size_t)row * LDSH + col);
            }
#pragma unroll
            for (int np = 0; np < NF / 2; np++) {
                int row = wn * WN + np * 16 + (lq >> 1) * 8 + lr;
                int col = k0 + (lq & 1) * 8;
                uint32_t r0, r1, r2, r3;
                ldsm_x4(r0, r1, r2, r3, Bbase + (size_t)row * LDSH + col);
                b[buf][2 * np][0] = r0; b[buf][2 * np][1] = r1;
                b[buf][2 * np + 1][0] = r2; b[buf][2 * np + 1][1] = r3;
            }
        };

        load_frag(0, 0);
#pragma unroll
        for (int ks = 0; ks < 8; ks++) {
            const int cur = ks & 1;
            if (ks < 7) load_frag(cur ^ 1, (ks + 1) * 16);
#pragma unroll
            for (int mf = 0; mf < MF; mf++)
#pragma unroll
                for (int nf = 0; nf < NF; nf++)
                    mma_f16(acc[mf][nf], a[cur][mf][0], a[cur][mf][1],
                            a[cur][mf][2], a[cur][mf][3],
                            b[cur][nf][0], b[cur][nf][1]);
        }
    }

    // ---- fused epilogue: exchange via smem, then gates ----
    __syncthreads();
    float* smf = (float*)sm;  // [128][EST]
#pragma unroll
    for (int nf = 0; nf < NF; nf++) {
        int col = wn * WN + nf * 8 + 2 * tg;
#pragma unroll
        for (int mf = 0; mf < MF; mf++) {
            int row = wm * WM + mf * 16 + g;
            *(float2*)&smf[(size_t)row * EST + col]       = make_float2(acc[mf][nf][0], acc[mf][nf][1]);
            *(float2*)&smf[(size_t)(row + 8) * EST + col] = make_float2(acc[mf][nf][2], acc[mf][nf][3]);
        }
    }
    __syncthreads();

    const int b_local = tid >> 1;
    const int bb = mbase + b_local;
    float rsum = 0.f;
#pragma unroll
    for (int i = 0; i < 16; i++) {
        int s_local = (tid & 1) * 16 + i;
        float4 q = *(float4*)&smf[(size_t)b_local * EST + 4 * s_local];
        float ci = fmaxf(q.x, 0.f);
        float cf = fmaxf(q.y, 0.f);
        float co = fmaxf(q.z, 0.f);
        float cg = fmaxf(q.w, 0.f);
        float ig = fast_sigmoid(ci);
        float fg = fast_sigmoid(cf);
        float og = fast_sigmoid(co);
        float gg = fast_tanh(cg);
        int s_glob = (nbase >> 2) + s_local;
        size_t cidx = (size_t)bb * S_DIM + s_glob;
        float cn = fg * cell[cidx] + ig * gg;
        float hnv = og * fast_tanh(cn);
        cell[cidx] = cn;
        // preds written once, never re-read: stream (evict-first)
        __stcs(&preds[((size_t)t * B_SZ + bb) * S_DIM + s_glob], hnv);
        hn[(size_t)bb * S_DIM + s_glob] = __float2half(hnv);
        rsum += hnv * rW[s_glob];
    }
    rsum += __shfl_xor_sync(0xffffffffu, rsum, 1);
    if (!(tid & 1)) atomicAdd(&rewards[t * B_SZ + bb], rsum);
}

// ---------------- precompute kernels ----------------
__global__ void pack_w_kernel(const float* __restrict__ fcW) {
    const int n1 = S_DIM * S_DIM;
    for (int i = blockIdx.x * blockDim.x + threadIdx.x; i < n1; i += gridDim.x * blockDim.x) {
        int nr = i / S_DIM, k = i % S_DIM;
        g_Wh[i] = __float2half(fcW[(size_t)nr * HS_DIM + k]);
    }
    const int n2 = S_DIM * ALP;
    for (int i = blockIdx.x * blockDim.x + threadIdx.x; i < n2; i += gridDim.x * blockDim.x) {
        int nr = i / ALP, c = i % ALP;
        float v = (c < A_DIM + P_DIM) ? fcW[(size_t)nr * HS_DIM + S_DIM + c] : 0.f;
        g_Wap[i] = __float2half(v);
    }
}

__global__ void al_init_kernel(const float* __restrict__ state,
                               const float* __restrict__ act,
                               const float* __restrict__ latent,
                               float* __restrict__ rewards,
                               const float* __restrict__ rb) {
    const int n1 = T_STEPS * B_SZ * ALP;
    for (int i = blockIdx.x * blockDim.x + threadIdx.x; i < n1; i += gridDim.x * blockDim.x) {
        int r = i / ALP, c = i % ALP;
        int t = r / B_SZ, b = r % B_SZ;
        float v;
        if (c < A_DIM)              v = act[((size_t)b * T_STEPS + t) * A_DIM + c];
        else if (c < A_DIM + P_DIM) v = latent[(size_t)b * P_DIM + (c - A_DIM)];
        else                        v = 0.f;
        g_al[i] = __float2half(v);
    }
    const int n2 = B_SZ * S_DIM;
    for (int i = blockIdx.x * blockDim.x + threadIdx.x; i < n2; i += gridDim.x * blockDim.x)
        g_s0[i] = __float2half(state[i]);
    for (int i = blockIdx.x * blockDim.x + threadIdx.x; i < T_STEPS * B_SZ;
         i += gridDim.x * blockDim.x)
        rewards[i] = rb[0];
}

__global__ void fc1fold_kernel(const float* __restrict__ fc1) {
    const int n = S_DIM * S_DIM;
    for (int i = blockIdx.x * blockDim.x + threadIdx.x; i < n; i += gridDim.x * blockDim.x) {
        int nr = i / S_DIM, k = i % S_DIM;
        g_fc1e[i] = __float2half(fc1[(size_t)nr * 2 * S_DIM + k] +
                                 fc1[(size_t)nr * 2 * S_DIM + S_DIM + k]);
    }
}

__global__ void ww_interleave_kernel(const float* __restrict__ WW) {
    const size_t n = (size_t)4 * S_DIM * S_DIM;
    for (size_t i = (size_t)blockIdx.x * blockDim.x + threadIdx.x; i < n;
         i += (size_t)gridDim.x * blockDim.x) {
        size_t nr = i / S_DIM, k = i % S_DIM;
        size_t s = nr >> 2, gate = nr & 3;
        g_WWi[i] = __float2half(WW[(gate * S_DIM + s) * S_DIM + k]);
    }
}

__global__ void conv_h_kernel(const float* __restrict__ src, __half* __restrict__ dst, int n) {
    for (int i = blockIdx.x * blockDim.x + threadIdx.x; i < n; i += gridDim.x * blockDim.x)
        dst[i] = __float2half(src[i]);
}

// ---------------- host orchestration ----------------
extern "C" void kernel_launch(void* const* d_in, const int* in_sizes, int n_in,
                              void* d_out, int out_size) {
    const float* state  = (const float*)d_in[0];
    const float* act    = (const float*)d_in[1];
    const float* latent = (const float*)d_in[2];
    const float* fcW    = (const float*)d_in[3];
    const float* fcb    = (const float*)d_in[4];
    const float* fc1    = (const float*)d_in[5];
    const float* fc2    = (const float*)d_in[6];
    const float* WW     = (const float*)d_in[7];
    const float* rW     = (const float*)d_in[8];
    const float* rb     = (const float*)d_in[9];

    float* out     = (float*)d_out;
    float* preds   = out;
    float* rewards = out + PRED_ELEMS;

    __half *p_Wh, *p_Wap, *p_fc1e, *p_fc2, *p_WW, *p_al, *p_s0, *p_hn, *p_h, *p_x1, *p_x2;
    float *p_c, *p_ab;
    cudaGetSymbolAddress((void**)&p_Wh,   g_Wh);
    cudaGetSymbolAddress((void**)&p_Wap,  g_Wap);
    cudaGetSymbolAddress((void**)&p_fc1e, g_fc1e);
    cudaGetSymbolAddress((void**)&p_fc2,  g_fc2);
    cudaGetSymbolAddress((void**)&p_WW,   g_WWi);
    cudaGetSymbolAddress((void**)&p_al,   g_al);
    cudaGetSymbolAddress((void**)&p_s0,   g_s0);
    cudaGetSymbolAddress((void**)&p_hn,   g_hn);
    cudaGetSymbolAddress((void**)&p_h,    g_h);
    cudaGetSymbolAddress((void**)&p_x1,   g_x1);
    cudaGetSymbolAddress((void**)&p_x2,   g_x2);
    cudaGetSymbolAddress((void**)&p_c,    g_c);
    cudaGetSymbolAddress((void**)&p_ab,   g_abias);

    constexpr int SMEM_S = 4 * (64 + 64)   * LDSH * (int)sizeof(__half);  // 139264
    constexpr int SMEM_W = 3 * (128 + 128) * LDSH * (int)sizeof(__half);  // 208896
    cudaFuncSetAttribute((const void*)gemm_hmma<64, 64, 2, 4, 4, true>,
                         cudaFuncAttributeMaxDynamicSharedMemorySize, SMEM_S);
    cudaFuncSetAttribute((const void*)gemm_hmma<64, 64, 2, 4, 4, false>,
                         cudaFuncAttributeMaxDynamicSharedMemorySize, SMEM_S);
    cudaFuncSetAttribute((const void*)ww_gates_fused,
                         cudaFuncAttributeMaxDynamicSharedMemorySize, SMEM_W);

    const dim3 blk(256);
    const dim3 gS(S_DIM / 64, B_SZ / 64);            // (32,4) = 128 CTAs
    const dim3 gAB(S_DIM / 64, T_STEPS * B_SZ / 64); // (32,128) abias GEMM
    const dim3 gW(4 * S_DIM / 128, B_SZ / 128);      // (64,2) = 128 CTAs

    // --- precompute; launch #4 = initial fc GEMM (profiled) ---
    pack_w_kernel<<<1024, 256>>>(fcW);                                 // 1
    al_init_kernel<<<1024, 256>>>(state, act, latent, rewards, rb);    // 2
    gemm_hmma<64, 64, 2, 4, 4, false><<<gAB, blk, SMEM_S>>>(           // 3: abias
        p_al, p_Wap, p_ab, nullptr, fcb, nullptr, S_DIM, ALP);
    gemm_hmma<64, 64, 2, 4, 4, true><<<gS, blk, SMEM_S>>>(             // 4 (PROFILED)
        p_s0, p_Wh, p_c, p_h, nullptr, p_ab, S_DIM, S_DIM);
    fc1fold_kernel<<<1024, 256>>>(fc1);                                // 5
    ww_interleave_kernel<<<2048, 256>>>(WW);                           // 6
    conv_h_kernel<<<1024, 256>>>(fc2, p_fc2, S_DIM * S_DIM);           // 7

    for (int t = 0; t < T_STEPS; t++) {
        gemm_hmma<64, 64, 2, 4, 4, true><<<gS, blk, SMEM_S>>>(
            p_h, p_fc1e, nullptr, p_x1, nullptr, nullptr, S_DIM, S_DIM);
        gemm_hmma<64, 64, 2, 4, 4, true><<<gS, blk, SMEM_S>>>(
            p_x1, p_fc2, nullptr, p_x2, nullptr, nullptr, S_DIM, S_DIM);
        ww_gates_fused<<<gW, blk, SMEM_W>>>(p_x2, p_WW, p_c, p_hn, preds, rewards, rW, t);
        if (t < T_STEPS - 1)
            gemm_hmma<64, 64, 2, 4, 4, true><<<gS, blk, SMEM_S>>>(
                p_hn, p_Wh, nullptr, p_h, nullptr, p_ab + (size_t)t * B_SZ * S_DIM,
                S_DIM, S_DIM);
    }
}

// round 14
// speedup vs baseline: 1.3457x; 1.0312x over previous
#include <cuda_runtime.h>
#include <cuda_fp16.h>
#include <cstdint>
#include <math.h>

#define S_DIM 2048
#define A_DIM 64
#define P_DIM 128
#define B_SZ 256
#define T_STEPS 32
#define HS_DIM (S_DIM + A_DIM + P_DIM)   // 2240
#define ALP 256                          // padded K for act/latent GEMM
#define PRED_ELEMS ((size_t)T_STEPS * B_SZ * S_DIM)

// ---------------- device scratch (static, no allocations) ----------------
__device__ __half g_Wh   [S_DIM * S_DIM];
__device__ __half g_Wap  [S_DIM * ALP];
__device__ __half g_fc1e [S_DIM * S_DIM];
__device__ __half g_fc2  [S_DIM * S_DIM];
__device__ __half g_WWi  [4 * S_DIM * S_DIM];
__device__ __half g_al   [T_STEPS * B_SZ * ALP];
__device__ __half g_s0   [B_SZ * S_DIM];
__device__ float  g_abias[T_STEPS * B_SZ * S_DIM];
__device__ __half g_hn   [B_SZ * S_DIM];
__device__ __half g_h    [B_SZ * S_DIM];
__device__ __half g_x1   [B_SZ * S_DIM];
__device__ __half g_x2   [B_SZ * S_DIM];
__device__ float  g_c    [B_SZ * S_DIM];

// ---------------- helpers ----------------
__device__ __forceinline__ void cp16(void* sdst, const void* gsrc) {
    unsigned s = (unsigned)__cvta_generic_to_shared(sdst);
    asm volatile("cp.async.cg.shared.global [%0], [%1], 16;\n" :: "r"(s), "l"(gsrc));
}

__device__ __forceinline__ void ldsm_x4(uint32_t& r0, uint32_t& r1, uint32_t& r2, uint32_t& r3,
                                        const __half* p) {
    uint32_t a = (uint32_t)__cvta_generic_to_shared(p);
    asm volatile("ldmatrix.sync.aligned.m8n8.x4.shared.b16 {%0,%1,%2,%3}, [%4];\n"
                 : "=r"(r0), "=r"(r1), "=r"(r2), "=r"(r3) : "r"(a));
}

__device__ __forceinline__ void mma_f16(float c[4],
                                        uint32_t a0, uint32_t a1, uint32_t a2, uint32_t a3,
                                        uint32_t b0, uint32_t b1) {
    asm volatile(
        "mma.sync.aligned.m16n8k16.row.col.f32.f16.f16.f32 "
        "{%0,%1,%2,%3}, {%4,%5,%6,%7}, {%8,%9}, {%0,%1,%2,%3};\n"
        : "+f"(c[0]), "+f"(c[1]), "+f"(c[2]), "+f"(c[3])
        : "r"(a0), "r"(a1), "r"(a2), "r"(a3), "r"(b0), "r"(b1));
}

__device__ __forceinline__ float fast_sigmoid(float x) {
    return __fdividef(1.f, 1.f + __expf(-x));
}
__device__ __forceinline__ float fast_tanh(float x) {
    return __fdividef(2.f, 1.f + __expf(-2.f * x)) - 1.f;
}

#define LDSH 136   // halves per smem row (128 data + 8 pad); 272 B

// ================= generic fp16 HMMA GEMM with PDL =================
// out = [relu](A @ B^T + colBias + elemBias). A:[M,K], B:[N,K] fp16 row-major.
// Prologue: B (weights, independent of predecessor) prefetched BEFORE
// cudaGridDependencySynchronize(); A loads after. Trigger after final stores.
template<int BM, int BN, int WR, int WC, int NSTG, bool RELU>
__global__ void __launch_bounds__(256) gemm_hmma(
    const __half* __restrict__ A, const __half* __restrict__ Bm,
    float* __restrict__ outF, __half* __restrict__ outH,
    const float* __restrict__ colBias, const float* __restrict__ elemBias,
    int N, int K)
{
    constexpr int NTH = WR * WC * 32;
    constexpr int WM = BM / WR, WN = BN / WC;
    constexpr int MF = WM / 16, NF = WN / 8;
    constexpr int ROWS = BM + BN;
    constexpr int ITER  = ROWS * 16 / NTH;
    constexpr int ITERA = BM * 16 / NTH;
    constexpr int ITERB = BN * 16 / NTH;

    extern __shared__ __half sm[];

    const int tid  = threadIdx.x;
    const int warp = tid >> 5;
    const int lane = tid & 31;
    const int wm = warp / WC;
    const int wn = warp % WC;
    const int g  = lane >> 2;
    const int tg = lane & 3;
    const int lr = lane & 7;
    const int lq = lane >> 3;

    const int mbase = blockIdx.y * BM;
    const int nbase = blockIdx.x * BN;
    const __half* Ab = A  + (size_t)mbase * K;
    const __half* Bb = Bm + (size_t)nbase * K;
    const int nk = K >> 7;

    float acc[MF][NF][4];
#pragma unroll
    for (int i = 0; i < MF; i++)
#pragma unroll
        for (int j = 0; j < NF; j++)
#pragma unroll
            for (int e = 0; e < 4; e++) acc[i][j][e] = 0.f;

    auto load_B = [&](int st, int kb) {
        const int k0 = kb * 128;
        __half* Bo = sm + (size_t)st * ROWS * LDSH + (size_t)BM * LDSH;
#pragma unroll
        for (int i = 0; i < ITERB; i++) {
            int id  = tid + i * NTH;
            int row = id >> 4;
            int kc  = (id & 15) * 8;
            cp16(Bo + (size_t)row * LDSH + kc, Bb + (size_t)row * K + k0 + kc);
        }
    };
    auto load_A = [&](int st, int kb) {
        const int k0 = kb * 128;
        __half* Ao = sm + (size_t)st * ROWS * LDSH;
#pragma unroll
        for (int i = 0; i < ITERA; i++) {
            int id  = tid + i * NTH;
            int row = id >> 4;
            int kc  = (id & 15) * 8;
            cp16(Ao + (size_t)row * LDSH + kc, Ab + (size_t)row * K + k0 + kc);
        }
    };
    auto load_stage = [&](int st, int kb) {
        const int k0 = kb * 128;
        __half* Ao = sm + (size_t)st * ROWS * LDSH;
        __half* Bo = Ao + (size_t)BM * LDSH;
#pragma unroll
        for (int i = 0; i < ITER; i++) {
            int id  = tid + i * NTH;
            int row = id >> 4;
            int kc  = (id & 15) * 8;
            if (row < BM)
                cp16(Ao + (size_t)row * LDSH + kc, Ab + (size_t)row * K + k0 + kc);
            else
                cp16(Bo + (size_t)(row - BM) * LDSH + kc,
                     Bb + (size_t)(row - BM) * K + k0 + kc);
        }
        asm volatile("cp.async.commit_group;\n" ::: "memory");
    };

    // prologue: weights (B) first — independent of predecessor kernel
#pragma unroll
    for (int s = 0; s < NSTG - 1; s++)
        if (s < nk) load_B(s, s);

#if __CUDA_ARCH__ >= 900
    cudaGridDependencySynchronize();
#endif

    // A loads; group s contains (all prologue B if s==0) + A_s — in-order retire
#pragma unroll
    for (int s = 0; s < NSTG - 1; s++)
        if (s < nk) {
            load_A(s, s);
            asm volatile("cp.async.commit_group;\n" ::: "memory");
        }

    uint32_t a[2][MF][4];
    uint32_t b[2][NF][2];

    for (int kb = 0; kb < nk; kb++) {
        const int rem = nk - 1 - kb;
        const int allow = rem < NSTG - 2 ? rem : NSTG - 2;
        if (allow >= 2)      asm volatile("cp.async.wait_group 2;\n" ::: "memory");
        else if (allow == 1) asm volatile("cp.async.wait_group 1;\n" ::: "memory");
        else                 asm volatile("cp.async.wait_group 0;\n" ::: "memory");
        __syncthreads();

        if (kb + NSTG - 1 < nk) load_stage((kb + NSTG - 1) % NSTG, kb + NSTG - 1);

        const int st = kb % NSTG;
        const __half* Abase = sm + (size_t)st * ROWS * LDSH;
        const __half* Bbase = Abase + (size_t)BM * LDSH;

        auto load_frag = [&](int buf, int k0) {
#pragma unroll
            for (int mf = 0; mf < MF; mf++) {
                int row = wm * WM + mf * 16 + (lq & 1) * 8 + lr;
                int col = k0 + (lq >> 1) * 8;
                ldsm_x4(a[buf][mf][0], a[buf][mf][1], a[buf][mf][2], a[buf][mf][3],
                        Abase + (size_t)row * LDSH + col);
            }
#pragma unroll
            for (int np = 0; np < NF / 2; np++) {
                int row = wn * WN + np * 16 + (lq >> 1) * 8 + lr;
                int col = k0 + (lq & 1) * 8;
                uint32_t r0, r1, r2, r3;
                ldsm_x4(r0, r1, r2, r3, Bbase + (size_t)row * LDSH + col);
                b[buf][2 * np][0] = r0; b[buf][2 * np][1] = r1;
                b[buf][2 * np + 1][0] = r2; b[buf][2 * np + 1][1] = r3;
            }
        };

        load_frag(0, 0);
#pragma unroll
        for (int ks = 0; ks < 8; ks++) {
            const int cur = ks & 1;
            if (ks < 7) load_frag(cur ^ 1, (ks + 1) * 16);
#pragma unroll
            for (int mf = 0; mf < MF; mf++)
#pragma unroll
                for (int nf = 0; nf < NF; nf++)
                    mma_f16(acc[mf][nf], a[cur][mf][0], a[cur][mf][1],
                            a[cur][mf][2], a[cur][mf][3],
                            b[cur][nf][0], b[cur][nf][1]);
        }
    }

    // epilogue
#pragma unroll
    for (int nf = 0; nf < NF; nf++) {
        int col = nbase + wn * WN + nf * 8 + 2 * tg;
        float cb0 = colBias ? colBias[col]     : 0.f;
        float cb1 = colBias ? colBias[col + 1] : 0.f;
#pragma unroll
        for (int mf = 0; mf < MF; mf++) {
            int row = mbase + wm * WM + mf * 16 + g;
            size_t o0 = (size_t)row * N + col;
            size_t o1 = (size_t)(row + 8) * N + col;
            float e00 = 0.f, e01 = 0.f, e10 = 0.f, e11 = 0.f;
            if (elemBias) {
                float2 ea = __ldcs((const float2*)(elemBias + o0));
                float2 eb = __ldcs((const float2*)(elemBias + o1));
                e00 = ea.x; e01 = ea.y; e10 = eb.x; e11 = eb.y;
            }
            float v00 = acc[mf][nf][0] + cb0 + e00;
            float v01 = acc[mf][nf][1] + cb1 + e01;
            float v10 = acc[mf][nf][2] + cb0 + e10;
            float v11 = acc[mf][nf][3] + cb1 + e11;
            if (RELU) {
                v00 = fmaxf(v00, 0.f); v01 = fmaxf(v01, 0.f);
                v10 = fmaxf(v10, 0.f); v11 = fmaxf(v11, 0.f);
            }
            if (outF) {
                *(float2*)(outF + o0) = make_float2(v00, v01);
                *(float2*)(outF + o1) = make_float2(v10, v11);
            }
            if (outH) {
                *(__half2*)(outH + o0) = __floats2half2_rn(v00, v01);
                *(__half2*)(outH + o1) = __floats2half2_rn(v10, v11);
            }
        }
    }

#if __CUDA_ARCH__ >= 900
    cudaTriggerProgrammaticLaunchCompletion();
#endif
}

// ================= WW GEMM fused with LSTM gates / reward (PDL) =================
__global__ void __launch_bounds__(256) ww_gates_fused(
    const __half* __restrict__ A,       // x2 [256, 2048]
    const __half* __restrict__ Bm,      // WW interleaved [8192, 2048]
    float* __restrict__ cell,
    __half* __restrict__ hn,
    float* __restrict__ preds,
    float* __restrict__ rewards,
    const float* __restrict__ rW, int t)
{
    constexpr int BM = 128, BN = 128, WR = 2, WC = 4;
    constexpr int NTH = 256;
    constexpr int NSTG = 3;
    constexpr int WM = BM / WR, WN = BN / WC;   // 64, 32
    constexpr int MF = WM / 16, NF = WN / 8;    // 4, 4
    constexpr int ROWS = BM + BN;
    constexpr int ITER  = ROWS * 16 / NTH;      // 16
    constexpr int ITERA = BM * 16 / NTH;        // 8
    constexpr int ITERB = BN * 16 / NTH;        // 8
    constexpr int K = S_DIM;
    constexpr int nk = K / 128;                 // 16
    constexpr int EST = 132;

    extern __shared__ __half sm[];

    const int tid  = threadIdx.x;
    const int warp = tid >> 5;
    const int lane = tid & 31;
    const int wm = warp / WC;
    const int wn = warp % WC;
    const int g  = lane >> 2;
    const int tg = lane & 3;
    const int lr = lane & 7;
    const int lq = lane >> 3;

    const int mbase = blockIdx.y * BM;
    const int nbase = blockIdx.x * BN;
    const __half* Ab = A  + (size_t)mbase * K;
    const __half* Bb = Bm + (size_t)nbase * K;

    float acc[MF][NF][4];
#pragma unroll
    for (int i = 0; i < MF; i++)
#pragma unroll
        for (int j = 0; j < NF; j++)
#pragma unroll
            for (int e = 0; e < 4; e++) acc[i][j][e] = 0.f;

    auto load_B = [&](int st, int kb) {
        const int k0 = kb * 128;
        __half* Bo = sm + (size_t)st * ROWS * LDSH + (size_t)BM * LDSH;
#pragma unroll
        for (int i = 0; i < ITERB; i++) {
            int id  = tid + i * NTH;
            int row = id >> 4;
            int kc  = (id & 15) * 8;
            cp16(Bo + (size_t)row * LDSH + kc, Bb + (size_t)row * K + k0 + kc);
        }
    };
    auto load_A = [&](int st, int kb) {
        const int k0 = kb * 128;
        __half* Ao = sm + (size_t)st * ROWS * LDSH;
#pragma unroll
        for (int i = 0; i < ITERA; i++) {
            int id  = tid + i * NTH;
            int row = id >> 4;
            int kc  = (id & 15) * 8;
            cp16(Ao + (size_t)row * LDSH + kc, Ab + (size_t)row * K + k0 + kc);
        }
    };
    auto load_stage = [&](int st, int kb) {
        const int k0 = kb * 128;
        __half* Ao = sm + (size_t)st * ROWS * LDSH;
        __half* Bo = Ao + (size_t)BM * LDSH;
#pragma unroll
        for (int i = 0; i < ITER; i++) {
            int id  = tid + i * NTH;
            int row = id >> 4;
            int kc  = (id & 15) * 8;
            if (row < BM)
                cp16(Ao + (size_t)row * LDSH + kc, Ab + (size_t)row * K + k0 + kc);
            else
                cp16(Bo + (size_t)(row - BM) * LDSH + kc,
                     Bb + (size_t)(row - BM) * K + k0 + kc);
        }
        asm volatile("cp.async.commit_group;\n" ::: "memory");
    };

    load_B(0, 0);
    load_B(1, 1);
#if __CUDA_ARCH__ >= 900
    cudaGridDependencySynchronize();
#endif
    load_A(0, 0);
    asm volatile("cp.async.commit_group;\n" ::: "memory");
    load_A(1, 1);
    asm volatile("cp.async.commit_group;\n" ::: "memory");

    uint32_t a[2][MF][4];
    uint32_t b[2][NF][2];

    for (int kb = 0; kb < nk; kb++) {
        const int rem = nk - 1 - kb;
        const int allow = rem < NSTG - 2 ? rem : NSTG - 2;
        if (allow >= 1) asm volatile("cp.async.wait_group 1;\n" ::: "memory");
        else            asm volatile("cp.async.wait_group 0;\n" ::: "memory");
        __syncthreads();

        if (kb + 2 < nk) load_stage((kb + 2) % NSTG, kb + 2);

        const int st = kb % NSTG;
        const __half* Abase = sm + (size_t)st * ROWS * LDSH;
        const __half* Bbase = Abase + (size_t)BM * LDSH;

        auto load_frag = [&](int buf, int k0) {
#pragma unroll
            for (int mf = 0; mf < MF; mf++) {
                int row = wm * WM + mf * 16 + (lq & 1) * 8 + lr;
                int col = k0 + (lq >> 1) * 8;
                ldsm_x4(a[buf][mf][0], a[buf][mf][1], a[buf][mf][2], a[buf][mf][3],
                        Abase + (size_t)row * LDSH + col);
            }
#pragma unroll
            for (int np = 0; np < NF / 2; np++) {
                int row = wn * WN + np * 16 + (lq >> 1) * 8 + lr;
                int col = k0 + (lq & 1) * 8;
                uint32_t r0, r1, r2, r3;
                ldsm_x4(r0, r1, r2, r3, Bbase + (size_t)row * LDSH + col);
                b[buf][2 * np][0] = r0; b[buf][2 * np][1] = r1;
                b[buf][2 * np + 1][0] = r2; b[buf][2 * np + 1][1] = r3;
            }
        };

        load_frag(0, 0);
#pragma unroll
        for (int ks = 0; ks < 8; ks++) {
            const int cur = ks & 1;
            if (ks < 7) load_frag(cur ^ 1, (ks + 1) * 16);
#pragma unroll
            for (int mf = 0; mf < MF; mf++)
#pragma unroll
                for (int nf = 0; nf < NF; nf++)
                    mma_f16(acc[mf][nf], a[cur][mf][0], a[cur][mf][1],
                            a[cur][mf][2], a[cur][mf][3],
                            b[cur][nf][0], b[cur][nf][1]);
        }
    }

    // ---- fused epilogue: exchange via smem, then gates ----
    __syncthreads();
    float* smf = (float*)sm;  // [128][EST]
#pragma unroll
    for (int nf = 0; nf < NF; nf++) {
        int col = wn * WN + nf * 8 + 2 * tg;
#pragma unroll
        for (int mf = 0; mf < MF; mf++) {
            int row = wm * WM + mf * 16 + g;
            *(float2*)&smf[(size_t)row * EST + col]       = make_float2(acc[mf][nf][0], acc[mf][nf][1]);
            *(float2*)&smf[(size_t)(row + 8) * EST + col] = make_float2(acc[mf][nf][2], acc[mf][nf][3]);
        }
    }
    __syncthreads();

    const int b_local = tid >> 1;
    const int bb = mbase + b_local;
    float rsum = 0.f;
#pragma unroll
    for (int i = 0; i < 16; i++) {
        int s_local = (tid & 1) * 16 + i;
        float4 q = *(float4*)&smf[(size_t)b_local * EST + 4 * s_local];
        float ci = fmaxf(q.x, 0.f);
        float cf = fmaxf(q.y, 0.f);
        float co = fmaxf(q.z, 0.f);
        float cg = fmaxf(q.w, 0.f);
        float ig = fast_sigmoid(ci);
        float fg = fast_sigmoid(cf);
        float og = fast_sigmoid(co);
        float gg = fast_tanh(cg);
        int s_glob = (nbase >> 2) + s_local;
        size_t cidx = (size_t)bb * S_DIM + s_glob;
        float cn = fg * cell[cidx] + ig * gg;
        float hnv = og * fast_tanh(cn);
        cell[cidx] = cn;
        __stcs(&preds[((size_t)t * B_SZ + bb) * S_DIM + s_glob], hnv);
        hn[(size_t)bb * S_DIM + s_glob] = __float2half(hnv);
        rsum += hnv * rW[s_glob];
    }
    rsum += __shfl_xor_sync(0xffffffffu, rsum, 1);
    if (!(tid & 1)) atomicAdd(&rewards[t * B_SZ + bb], rsum);

#if __CUDA_ARCH__ >= 900
    cudaTriggerProgrammaticLaunchCompletion();
#endif
}

// ---------------- precompute kernels ----------------
__global__ void pack_w_kernel(const float* __restrict__ fcW) {
    const int n1 = S_DIM * S_DIM;
    for (int i = blockIdx.x * blockDim.x + threadIdx.x; i < n1; i += gridDim.x * blockDim.x) {
        int nr = i / S_DIM, k = i % S_DIM;
        g_Wh[i] = __float2half(fcW[(size_t)nr * HS_DIM + k]);
    }
    const int n2 = S_DIM * ALP;
    for (int i = blockIdx.x * blockDim.x + threadIdx.x; i < n2; i += gridDim.x * blockDim.x) {
        int nr = i / ALP, c = i % ALP;
        float v = (c < A_DIM + P_DIM) ? fcW[(size_t)nr * HS_DIM + S_DIM + c] : 0.f;
        g_Wap[i] = __float2half(v);
    }
}

__global__ void al_init_kernel(const float* __restrict__ state,
                               const float* __restrict__ act,
                               const float* __restrict__ latent,
                               float* __restrict__ rewards,
                               const float* __restrict__ rb) {
    const int n1 = T_STEPS * B_SZ * ALP;
    for (int i = blockIdx.x * blockDim.x + threadIdx.x; i < n1; i += gridDim.x * blockDim.x) {
        int r = i / ALP, c = i % ALP;
        int t = r / B_SZ, b = r % B_SZ;
        float v;
        if (c < A_DIM)              v = act[((size_t)b * T_STEPS + t) * A_DIM + c];
        else if (c < A_DIM + P_DIM) v = latent[(size_t)b * P_DIM + (c - A_DIM)];
        else                        v = 0.f;
        g_al[i] = __float2half(v);
    }
    const int n2 = B_SZ * S_DIM;
    for (int i = blockIdx.x * blockDim.x + threadIdx.x; i < n2; i += gridDim.x * blockDim.x)
        g_s0[i] = __float2half(state[i]);
    for (int i = blockIdx.x * blockDim.x + threadIdx.x; i < T_STEPS * B_SZ;
         i += gridDim.x * blockDim.x)
        rewards[i] = rb[0];
}

__global__ void fc1fold_kernel(const float* __restrict__ fc1) {
    const int n = S_DIM * S_DIM;
    for (int i = blockIdx.x * blockDim.x + threadIdx.x; i < n; i += gridDim.x * blockDim.x) {
        int nr = i / S_DIM, k = i % S_DIM;
        g_fc1e[i] = __float2half(fc1[(size_t)nr * 2 * S_DIM + k] +
                                 fc1[(size_t)nr * 2 * S_DIM + S_DIM + k]);
    }
}

__global__ void ww_interleave_kernel(const float* __restrict__ WW) {
    const size_t n = (size_t)4 * S_DIM * S_DIM;
    for (size_t i = (size_t)blockIdx.x * blockDim.x + threadIdx.x; i < n;
         i += (size_t)gridDim.x * blockDim.x) {
        size_t nr = i / S_DIM, k = i % S_DIM;
        size_t s = nr >> 2, gate = nr & 3;
        g_WWi[i] = __float2half(WW[(gate * S_DIM + s) * S_DIM + k]);
    }
}

__global__ void conv_h_kernel(const float* __restrict__ src, __half* __restrict__ dst, int n) {
    for (int i = blockIdx.x * blockDim.x + threadIdx.x; i < n; i += gridDim.x * blockDim.x)
        dst[i] = __float2half(src[i]);
}

// ---------------- host orchestration ----------------
extern "C" void kernel_launch(void* const* d_in, const int* in_sizes, int n_in,
                              void* d_out, int out_size) {
    const float* state  = (const float*)d_in[0];
    const float* act    = (const float*)d_in[1];
    const float* latent = (const float*)d_in[2];
    const float* fcW    = (const float*)d_in[3];
    const float* fcb    = (const float*)d_in[4];
    const float* fc1    = (const float*)d_in[5];
    const float* fc2    = (const float*)d_in[6];
    const float* WW     = (const float*)d_in[7];
    const float* rW     = (const float*)d_in[8];
    const float* rb     = (const float*)d_in[9];

    float* out     = (float*)d_out;
    float* preds   = out;
    float* rewards = out + PRED_ELEMS;

    __half *p_Wh, *p_Wap, *p_fc1e, *p_fc2, *p_WW, *p_al, *p_s0, *p_hn, *p_h, *p_x1, *p_x2;
    float *p_c, *p_ab;
    cudaGetSymbolAddress((void**)&p_Wh,   g_Wh);
    cudaGetSymbolAddress((void**)&p_Wap,  g_Wap);
    cudaGetSymbolAddress((void**)&p_fc1e, g_fc1e);
    cudaGetSymbolAddress((void**)&p_fc2,  g_fc2);
    cudaGetSymbolAddress((void**)&p_WW,   g_WWi);
    cudaGetSymbolAddress((void**)&p_al,   g_al);
    cudaGetSymbolAddress((void**)&p_s0,   g_s0);
    cudaGetSymbolAddress((void**)&p_hn,   g_hn);
    cudaGetSymbolAddress((void**)&p_h,    g_h);
    cudaGetSymbolAddress((void**)&p_x1,   g_x1);
    cudaGetSymbolAddress((void**)&p_x2,   g_x2);
    cudaGetSymbolAddress((void**)&p_c,    g_c);
    cudaGetSymbolAddress((void**)&p_ab,   g_abias);

    constexpr int SMEM_S = 4 * (64 + 64)   * LDSH * (int)sizeof(__half);  // 139264
    constexpr int SMEM_W = 3 * (128 + 128) * LDSH * (int)sizeof(__half);  // 208896
    cudaFuncSetAttribute((const void*)gemm_hmma<64, 64, 2, 4, 4, true>,
                         cudaFuncAttributeMaxDynamicSharedMemorySize, SMEM_S);
    cudaFuncSetAttribute((const void*)gemm_hmma<64, 64, 2, 4, 4, false>,
                         cudaFuncAttributeMaxDynamicSharedMemorySize, SMEM_S);
    cudaFuncSetAttribute((const void*)ww_gates_fused,
                         cudaFuncAttributeMaxDynamicSharedMemorySize, SMEM_W);

    const dim3 blk(256);
    const dim3 gS(S_DIM / 64, B_SZ / 64);            // (32,4) = 128 CTAs
    const dim3 gAB(S_DIM / 64, T_STEPS * B_SZ / 64); // (32,128) abias GEMM
    const dim3 gW(4 * S_DIM / 128, B_SZ / 128);      // (64,2) = 128 CTAs

    // --- precompute; launch #4 = initial fc GEMM (profiled, plain launch) ---
    pack_w_kernel<<<1024, 256>>>(fcW);                                 // 1
    al_init_kernel<<<1024, 256>>>(state, act, latent, rewards, rb);    // 2
    gemm_hmma<64, 64, 2, 4, 4, false><<<gAB, blk, SMEM_S>>>(           // 3: abias
        p_al, p_Wap, p_ab, nullptr, fcb, nullptr, S_DIM, ALP);
    gemm_hmma<64, 64, 2, 4, 4, true><<<gS, blk, SMEM_S>>>(             // 4 (PROFILED)
        p_s0, p_Wh, p_c, p_h, nullptr, p_ab, S_DIM, S_DIM);
    fc1fold_kernel<<<1024, 256>>>(fc1);                                // 5
    ww_interleave_kernel<<<2048, 256>>>(WW);                           // 6
    conv_h_kernel<<<1024, 256>>>(fc2, p_fc2, S_DIM * S_DIM);           // 7

    // PDL launch configs
    cudaLaunchAttribute pdlAttr[1];
    pdlAttr[0].id = cudaLaunchAttributeProgrammaticStreamSerialization;
    pdlAttr[0].val.programmaticStreamSerializationAllowed = 1;

    cudaLaunchConfig_t cfgS = {};
    cfgS.gridDim = gS; cfgS.blockDim = blk; cfgS.dynamicSmemBytes = SMEM_S;
    cfgS.attrs = pdlAttr; cfgS.numAttrs = 1;

    cudaLaunchConfig_t cfgW = {};
    cfgW.gridDim = gW; cfgW.blockDim = blk; cfgW.dynamicSmemBytes = SMEM_W;
    cfgW.attrs = pdlAttr; cfgW.numAttrs = 1;

    for (int t = 0; t < T_STEPS; t++) {
        cudaLaunchKernelEx(&cfgS, gemm_hmma<64, 64, 2, 4, 4, true>,
                           (const __half*)p_h, (const __half*)p_fc1e,
                           (float*)nullptr, (__half*)p_x1,
                           (const float*)nullptr, (const float*)nullptr,
                           (int)S_DIM, (int)S_DIM);
        cudaLaunchKernelEx(&cfgS, gemm_hmma<64, 64, 2, 4, 4, true>,
                           (const __half*)p_x1, (const __half*)p_fc2,
                           (float*)nullptr, (__half*)p_x2,
                           (const float*)nullptr, (const float*)nullptr,
                           (int)S_DIM, (int)S_DIM);
        cudaLaunchKernelEx(&cfgW, ww_gates_fused,
                           (const __half*)p_x2, (const __half*)p_WW,
                           (float*)p_c, (__half*)p_hn,
                           (float*)preds, (float*)rewards,
                           (const float*)rW, (int)t);
        if (t < T_STEPS - 1)
            cudaLaunchKernelEx(&cfgS, gemm_hmma<64, 64, 2, 4, 4, true>,
                               (const __half*)p_hn, (const __half*)p_Wh,
                               (float*)nullptr, (__half*)p_h,
                               (const float*)nullptr,
                               (const float*)(p_ab + (size_t)t * B_SZ * S_DIM),
                               (int)S_DIM, (int)S_DIM);
    }
}